// round 1
// baseline (speedup 1.0000x reference)
#include <cuda_runtime.h>
#include <math.h>

#define Bn 2
#define Sn 2048
#define En 1024
#define Hn 16
#define Dn 64
#define Mn (Bn*Sn)    // 4096 rows for projections
#define BHn (Bn*Hn)   // 32
#define TP 68         // padded smem row stride (floats)

// Scratch (device globals — no allocation allowed)
__device__ float g_q[(size_t)BHn*Sn*Dn];
__device__ float g_k[(size_t)BHn*Sn*Dn];
__device__ float g_v[(size_t)BHn*Sn*Dn];
__device__ float g_ctx[(size_t)Mn*En];
__device__ float g_m[BHn*Sn];
__device__ float g_l[BHn*Sn];

// ---------------------------------------------------------------------------
// C[M,N] = A[M,K] * W[N,K]^T + bias   (torch Linear), K = N = 1024 here.
// mode 0: out row-major [M, En]
// mode 1: out in head-split layout [B, H, S, D]  (n = h*64+d, m = b*2048+s)
// ---------------------------------------------------------------------------
__global__ __launch_bounds__(256, 2)
void sgemm_nt(const float* __restrict__ A, const float* __restrict__ W,
              const float* __restrict__ bias, float* __restrict__ out, int mode)
{
    const int K = En;
    __shared__ float As[16][132];
    __shared__ float Bs[16][132];
    int tid = threadIdx.x;
    int m0 = blockIdx.y * 128, n0 = blockIdx.x * 128;
    int tr = (tid >> 4) << 3;   // thread row in tile (0..120)
    int tc = (tid & 15) << 3;   // thread col in tile
    int lr = tid >> 2;          // load row (0..63)
    int lc = (tid & 3) << 2;    // load k-offset (0,4,8,12)

    float acc[8][8];
#pragma unroll
    for (int i = 0; i < 8; i++)
#pragma unroll
        for (int j = 0; j < 8; j++) acc[i][j] = 0.f;

    for (int k0 = 0; k0 < K; k0 += 16) {
        float4 a0 = *(const float4*)(A + (size_t)(m0 + lr     ) * K + k0 + lc);
        float4 a1 = *(const float4*)(A + (size_t)(m0 + lr + 64) * K + k0 + lc);
        float4 b0 = *(const float4*)(W + (size_t)(n0 + lr     ) * K + k0 + lc);
        float4 b1 = *(const float4*)(W + (size_t)(n0 + lr + 64) * K + k0 + lc);
        __syncthreads();
        As[lc+0][lr] = a0.x; As[lc+1][lr] = a0.y; As[lc+2][lr] = a0.z; As[lc+3][lr] = a0.w;
        As[lc+0][lr+64] = a1.x; As[lc+1][lr+64] = a1.y; As[lc+2][lr+64] = a1.z; As[lc+3][lr+64] = a1.w;
        Bs[lc+0][lr] = b0.x; Bs[lc+1][lr] = b0.y; Bs[lc+2][lr] = b0.z; Bs[lc+3][lr] = b0.w;
        Bs[lc+0][lr+64] = b1.x; Bs[lc+1][lr+64] = b1.y; Bs[lc+2][lr+64] = b1.z; Bs[lc+3][lr+64] = b1.w;
        __syncthreads();
#pragma unroll
        for (int kk = 0; kk < 16; kk++) {
            float a[8], b[8];
            *(float4*)(a)     = *(const float4*)&As[kk][tr];
            *(float4*)(a + 4) = *(const float4*)&As[kk][tr + 4];
            *(float4*)(b)     = *(const float4*)&Bs[kk][tc];
            *(float4*)(b + 4) = *(const float4*)&Bs[kk][tc + 4];
#pragma unroll
            for (int i = 0; i < 8; i++)
#pragma unroll
                for (int j = 0; j < 8; j++)
                    acc[i][j] = fmaf(a[i], b[j], acc[i][j]);
        }
    }

#pragma unroll
    for (int i = 0; i < 8; i++) {
        int m = m0 + tr + i;
#pragma unroll
        for (int j = 0; j < 8; j++) {
            int n = n0 + tc + j;
            float v = acc[i][j] + bias[n];
            if (mode == 0) {
                out[(size_t)m * En + n] = v;
            } else {
                int h = n >> 6, d = n & 63;
                int b = m >> 11, s = m & 2047;
                out[(((size_t)b * Hn + h) * Sn + s) * Dn + d] = v;
            }
        }
    }
}

// ---------------------------------------------------------------------------
// Flash-style causal attention, pass 1: computes context (pre-output-proj)
// and saves per-row max (m) and denom (l) for pass 2.
// Grid: (S/64 q-tiles, B*H). 256 threads as 16x16, each owning a 4x4 tile.
// ---------------------------------------------------------------------------
__global__ __launch_bounds__(256, 2)
void attn_pass1(const float* __restrict__ Q, const float* __restrict__ Kg,
                const float* __restrict__ Vg, float* __restrict__ ctx,
                float* __restrict__ gm, float* __restrict__ gl)
{
    extern __shared__ float smf[];
    float* Qs  = smf;                 // [64][TP] row-major, Qs[r][d]
    float* Kts = smf + 64 * TP;       // [64][TP] transposed, Kts[d][c]
    float* Vs  = smf + 2 * 64 * TP;   // [64][TP] row-major, Vs[c][d]
    float* Ss  = smf + 3 * 64 * TP;   // [64][TP] probabilities P[r][c]

    int qt = blockIdx.x, bh = blockIdx.y;
    int q0 = qt * 64;
    const float* Qb = Q  + (size_t)bh * Sn * Dn;
    const float* Kb = Kg + (size_t)bh * Sn * Dn;
    const float* Vb = Vg + (size_t)bh * Sn * Dn;
    int tid = threadIdx.x, ty = tid >> 4, tx = tid & 15;

    // Load Q tile (64 rows x 64 d)
    for (int idx = tid; idx < 64 * 16; idx += 256) {
        int r = idx >> 4, c4 = (idx & 15) << 2;
        *(float4*)&Qs[r * TP + c4] = *(const float4*)&Qb[(size_t)(q0 + r) * Dn + c4];
    }

    float m_i[4], l_i[4], o[4][4];
#pragma unroll
    for (int i = 0; i < 4; i++) {
        m_i[i] = -1e30f; l_i[i] = 0.f;
#pragma unroll
        for (int j = 0; j < 4; j++) o[i][j] = 0.f;
    }

    for (int kt = 0; kt <= qt; kt++) {
        __syncthreads();
        // Load K (transposed) and V tiles
        for (int idx = tid; idx < 64 * 16; idx += 256) {
            int c = idx >> 4, d4 = (idx & 15) << 2;
            float4 kv = *(const float4*)&Kb[(size_t)(kt * 64 + c) * Dn + d4];
            Kts[(d4 + 0) * TP + c] = kv.x;
            Kts[(d4 + 1) * TP + c] = kv.y;
            Kts[(d4 + 2) * TP + c] = kv.z;
            Kts[(d4 + 3) * TP + c] = kv.w;
            *(float4*)&Vs[c * TP + d4] = *(const float4*)&Vb[(size_t)(kt * 64 + c) * Dn + d4];
        }
        __syncthreads();

        // Scores: s[i][j] = Q[row ty*4+i] . K[col tx*4+j]
        float s[4][4];
#pragma unroll
        for (int i = 0; i < 4; i++)
#pragma unroll
            for (int j = 0; j < 4; j++) s[i][j] = 0.f;

#pragma unroll 16
        for (int d = 0; d < 64; d++) {
            float4 kv = *(const float4*)&Kts[d * TP + (tx << 2)];
#pragma unroll
            for (int i = 0; i < 4; i++) {
                float qv = Qs[(ty * 4 + i) * TP + d];
                s[i][0] = fmaf(qv, kv.x, s[i][0]);
                s[i][1] = fmaf(qv, kv.y, s[i][1]);
                s[i][2] = fmaf(qv, kv.z, s[i][2]);
                s[i][3] = fmaf(qv, kv.w, s[i][3]);
            }
        }

        const float scale = 0.125f;  // 1/sqrt(64)
        if (kt == qt) {
#pragma unroll
            for (int i = 0; i < 4; i++) {
                int rr = q0 + ty * 4 + i;
#pragma unroll
                for (int j = 0; j < 4; j++) {
                    int cc = kt * 64 + (tx << 2) + j;
                    s[i][j] = (cc <= rr) ? s[i][j] * scale : -1e9f;
                }
            }
        } else {
#pragma unroll
            for (int i = 0; i < 4; i++)
#pragma unroll
                for (int j = 0; j < 4; j++) s[i][j] *= scale;
        }

        // Online softmax per row (16 consecutive lanes own one row)
#pragma unroll
        for (int i = 0; i < 4; i++) {
            float tmax = fmaxf(fmaxf(s[i][0], s[i][1]), fmaxf(s[i][2], s[i][3]));
#pragma unroll
            for (int off = 8; off > 0; off >>= 1)
                tmax = fmaxf(tmax, __shfl_xor_sync(0xffffffffu, tmax, off));
            float mnew = fmaxf(m_i[i], tmax);
            float fac  = __expf(m_i[i] - mnew);
            float rs = 0.f;
#pragma unroll
            for (int j = 0; j < 4; j++) { s[i][j] = __expf(s[i][j] - mnew); rs += s[i][j]; }
#pragma unroll
            for (int off = 8; off > 0; off >>= 1)
                rs += __shfl_xor_sync(0xffffffffu, rs, off);
            l_i[i] = l_i[i] * fac + rs;
            m_i[i] = mnew;
#pragma unroll
            for (int j = 0; j < 4; j++) o[i][j] *= fac;
        }

        // Stage probabilities for the PV product
#pragma unroll
        for (int i = 0; i < 4; i++)
            *(float4*)&Ss[(ty * 4 + i) * TP + (tx << 2)] =
                make_float4(s[i][0], s[i][1], s[i][2], s[i][3]);
        __syncthreads();

        // O += P @ V  (thread owns rows ty*4.., d-cols tx*4..)
#pragma unroll 16
        for (int c = 0; c < 64; c++) {
            float4 vv = *(const float4*)&Vs[c * TP + (tx << 2)];
#pragma unroll
            for (int i = 0; i < 4; i++) {
                float pv = Ss[(ty * 4 + i) * TP + c];
                o[i][0] = fmaf(pv, vv.x, o[i][0]);
                o[i][1] = fmaf(pv, vv.y, o[i][1]);
                o[i][2] = fmaf(pv, vv.z, o[i][2]);
                o[i][3] = fmaf(pv, vv.w, o[i][3]);
            }
        }
    }

    // Finalize: normalize and write context in [B,S,E] layout; save m,l
    int b = bh >> 4, h = bh & 15;
#pragma unroll
    for (int i = 0; i < 4; i++) {
        float inv = 1.f / l_i[i];
        int sg = q0 + ty * 4 + i;
        float4 ov = make_float4(o[i][0] * inv, o[i][1] * inv, o[i][2] * inv, o[i][3] * inv);
        *(float4*)&ctx[((size_t)b * Sn + sg) * En + h * Dn + (tx << 2)] = ov;
        if (tx == 0) {
            gm[bh * Sn + sg] = m_i[i];
            gl[bh * Sn + sg] = l_i[i];
        }
    }
}

// ---------------------------------------------------------------------------
// Pass 2: recompute scores per tile and write attn probabilities.
// Grid: (kt, qt, bh). Upper-triangular tiles (kt>qt) write zeros.
// ---------------------------------------------------------------------------
__global__ __launch_bounds__(256)
void attn_write(const float* __restrict__ Q, const float* __restrict__ Kg,
                const float* __restrict__ gm, const float* __restrict__ gl,
                float* __restrict__ attn)
{
    __shared__ float Qs[64 * TP];
    __shared__ float Kts[64 * TP];
    int kt = blockIdx.x, qt = blockIdx.y, bh = blockIdx.z;
    int tid = threadIdx.x, ty = tid >> 4, tx = tid & 15;
    int q0 = qt * 64;
    float* arow = attn + (size_t)bh * Sn * Sn;

    if (kt > qt) {
        float4 z = make_float4(0.f, 0.f, 0.f, 0.f);
        for (int idx = tid; idx < 64 * 16; idx += 256) {
            int r = idx >> 4, c4 = (idx & 15) << 2;
            *(float4*)&arow[(size_t)(q0 + r) * Sn + kt * 64 + c4] = z;
        }
        return;
    }

    const float* Qb = Q  + (size_t)bh * Sn * Dn;
    const float* Kb = Kg + (size_t)bh * Sn * Dn;
    for (int idx = tid; idx < 64 * 16; idx += 256) {
        int r = idx >> 4, c4 = (idx & 15) << 2;
        *(float4*)&Qs[r * TP + c4] = *(const float4*)&Qb[(size_t)(q0 + r) * Dn + c4];
        int c = r, d4 = c4;
        float4 kv = *(const float4*)&Kb[(size_t)(kt * 64 + c) * Dn + d4];
        Kts[(d4 + 0) * TP + c] = kv.x;
        Kts[(d4 + 1) * TP + c] = kv.y;
        Kts[(d4 + 2) * TP + c] = kv.z;
        Kts[(d4 + 3) * TP + c] = kv.w;
    }
    __syncthreads();

    float s[4][4];
#pragma unroll
    for (int i = 0; i < 4; i++)
#pragma unroll
        for (int j = 0; j < 4; j++) s[i][j] = 0.f;

#pragma unroll 16
    for (int d = 0; d < 64; d++) {
        float4 kv = *(const float4*)&Kts[d * TP + (tx << 2)];
#pragma unroll
        for (int i = 0; i < 4; i++) {
            float qv = Qs[(ty * 4 + i) * TP + d];
            s[i][0] = fmaf(qv, kv.x, s[i][0]);
            s[i][1] = fmaf(qv, kv.y, s[i][1]);
            s[i][2] = fmaf(qv, kv.z, s[i][2]);
            s[i][3] = fmaf(qv, kv.w, s[i][3]);
        }
    }

    const float scale = 0.125f;
#pragma unroll
    for (int i = 0; i < 4; i++) {
        int rr = q0 + ty * 4 + i;
        float mr  = gm[bh * Sn + rr];
        float inv = 1.f / gl[bh * Sn + rr];
        float4 p;
        float* pp = (float*)&p;
#pragma unroll
        for (int j = 0; j < 4; j++) {
            int cc = kt * 64 + (tx << 2) + j;
            float sv = (kt == qt && cc > rr) ? -1e9f : s[i][j] * scale;
            pp[j] = __expf(sv - mr) * inv;
        }
        *(float4*)&arow[(size_t)rr * Sn + kt * 64 + (tx << 2)] = p;
    }
}

// ---------------------------------------------------------------------------
extern "C" void kernel_launch(void* const* d_in, const int* in_sizes, int n_in,
                              void* d_out, int out_size)
{
    const float* query = (const float*)d_in[0];
    const float* key   = (const float*)d_in[1];
    const float* value = (const float*)d_in[2];
    // d_in[3] = mask (bool, causal tril) — applied analytically
    const float* Wq = (const float*)d_in[4];
    const float* bq = (const float*)d_in[5];
    const float* Wk = (const float*)d_in[6];
    const float* bk = (const float*)d_in[7];
    const float* Wv = (const float*)d_in[8];
    const float* bv = (const float*)d_in[9];
    const float* Wo = (const float*)d_in[10];
    const float* bo = (const float*)d_in[11];

    float *pq, *pk, *pv, *pctx, *pm, *pl;
    cudaGetSymbolAddress((void**)&pq,   g_q);
    cudaGetSymbolAddress((void**)&pk,   g_k);
    cudaGetSymbolAddress((void**)&pv,   g_v);
    cudaGetSymbolAddress((void**)&pctx, g_ctx);
    cudaGetSymbolAddress((void**)&pm,   g_m);
    cudaGetSymbolAddress((void**)&pl,   g_l);

    dim3 gg(En / 128, Mn / 128);  // (8, 32)
    sgemm_nt<<<gg, 256>>>(query, Wq, bq, pq, 1);
    sgemm_nt<<<gg, 256>>>(key,   Wk, bk, pk, 1);
    sgemm_nt<<<gg, 256>>>(value, Wv, bv, pv, 1);

    size_t smem1 = (size_t)4 * 64 * TP * sizeof(float);  // 69632 B
    cudaFuncSetAttribute(attn_pass1, cudaFuncAttributeMaxDynamicSharedMemorySize, (int)smem1);
    attn_pass1<<<dim3(Sn / 64, BHn), 256, smem1>>>(pq, pk, pv, pctx, pm, pl);

    const size_t OUT_ELEMS  = (size_t)Bn * Sn * En;       //   4,194,304
    const size_t ATTN_ELEMS = (size_t)BHn * Sn * Sn;      // 134,217,728
    float* outp  = (float*)d_out;
    float* attnp = nullptr;
    if ((size_t)out_size >= OUT_ELEMS + ATTN_ELEMS) {
        attnp = outp + OUT_ELEMS;                 // tuple (out, attn) concatenated
    } else if ((size_t)out_size == ATTN_ELEMS) {
        attnp = outp; outp = nullptr;             // attn only
    }

    if (attnp)
        attn_write<<<dim3(Sn / 64, Sn / 64, BHn), 256>>>(pq, pk, pm, pl, attnp);
    if (outp)
        sgemm_nt<<<gg, 256>>>(pctx, Wo, bo, outp, 0);
}

// round 3
// speedup vs baseline: 1.3419x; 1.3419x over previous
#include <cuda_runtime.h>
#include <cuda_bf16.h>
#include <math.h>
#include <stdint.h>

#define Bn 2
#define Sn 2048
#define En 1024
#define Hn 16
#define Dn 64
#define Mn (Bn*Sn)    // 4096 rows for projections
#define BHn (Bn*Hn)   // 32
#define TP 68         // padded smem row stride (floats)

// Scratch (device globals — no allocation allowed)
__device__ float g_q[(size_t)BHn*Sn*Dn];
__device__ float g_k[(size_t)BHn*Sn*Dn];
__device__ float g_v[(size_t)BHn*Sn*Dn];
__device__ float g_ctx[(size_t)Mn*En];
__device__ float g_m[BHn*Sn];
__device__ float g_l[BHn*Sn];
// bf16 split scratch
__device__ __nv_bfloat16 g_Ahi[(size_t)Mn*En];
__device__ __nv_bfloat16 g_Alo[(size_t)Mn*En];
__device__ __nv_bfloat16 g_Whi[(size_t)En*En];
__device__ __nv_bfloat16 g_Wlo[(size_t)En*En];

// ===========================================================================
// PTX helpers — ONLY base-target (compute_103-safe) instructions:
// cp.async (sm_80), ldmatrix (sm_75), mma.sync bf16 (sm_80).
// ===========================================================================
__device__ __forceinline__ uint32_t smem_u32(const void* p) {
    uint32_t a;
    asm("{ .reg .u64 t; cvta.to.shared.u64 t, %1; cvt.u32.u64 %0, t; }"
        : "=r"(a) : "l"(p));
    return a;
}
#define CP16(dst, src) \
    asm volatile("cp.async.cg.shared.global [%0], [%1], 16;\n" :: "r"(dst), "l"(src))
#define CP_COMMIT() asm volatile("cp.async.commit_group;\n" ::)
#define CP_WAIT0()  asm volatile("cp.async.wait_group 0;\n" ::)
#define CP_WAIT1()  asm volatile("cp.async.wait_group 1;\n" ::)
#define LDSM4(R0, R1, R2, R3, A) \
    asm volatile("ldmatrix.sync.aligned.m8n8.x4.shared.b16 {%0,%1,%2,%3}, [%4];" \
                 : "=r"(R0), "=r"(R1), "=r"(R2), "=r"(R3) : "r"(A))

__device__ __forceinline__ void mma16816(float* c, const uint32_t* a, const uint32_t* b) {
    asm volatile(
        "mma.sync.aligned.m16n8k16.row.col.f32.bf16.bf16.f32 "
        "{%0,%1,%2,%3}, {%4,%5,%6,%7}, {%8,%9}, {%0,%1,%2,%3};"
        : "+f"(c[0]), "+f"(c[1]), "+f"(c[2]), "+f"(c[3])
        : "r"(a[0]), "r"(a[1]), "r"(a[2]), "r"(a[3]), "r"(b[0]), "r"(b[1]));
}

// ===========================================================================
// Split fp32 -> (hi, lo) bf16 pair.  n4 = n/4 float4 chunks.
// ===========================================================================
__global__ void split_bf16(const float4* __restrict__ x,
                           __nv_bfloat162* __restrict__ hi,
                           __nv_bfloat162* __restrict__ lo, int n4)
{
    int i = blockIdx.x * blockDim.x + threadIdx.x;
    if (i >= n4) return;
    float4 v = x[i];
    __nv_bfloat16 h0 = __float2bfloat16(v.x), h1 = __float2bfloat16(v.y);
    __nv_bfloat16 h2 = __float2bfloat16(v.z), h3 = __float2bfloat16(v.w);
    hi[i * 2 + 0] = __halves2bfloat162(h0, h1);
    hi[i * 2 + 1] = __halves2bfloat162(h2, h3);
    lo[i * 2 + 0] = __halves2bfloat162(
        __float2bfloat16(v.x - __bfloat162float(h0)),
        __float2bfloat16(v.y - __bfloat162float(h1)));
    lo[i * 2 + 1] = __halves2bfloat162(
        __float2bfloat16(v.z - __bfloat162float(h2)),
        __float2bfloat16(v.w - __bfloat162float(h3)));
}

// ===========================================================================
// Tensor-core GEMM via mma.sync (legacy HMMA path, compute_103-safe):
// C[m][n] = sum_k A[m][k]*W[n][k] + bias[n]
// 3-term bf16 split: Ah*Wh + Ah*Wl + Al*Wh, fp32 accum in registers.
// 128x128 CTA tile, 8 warps (4x2), warp tile 32x64, K-chunk 32,
// cp.async double buffering. 80B smem row stride => conflict-free ldmatrix.
// ===========================================================================
#define KC     32              // k elems per stage
#define TROW   80              // bytes per smem row (32 bf16 padded to 40)
#define TTEN   (128 * TROW)    // one 128xKC bf16 tensor  = 10240 B
#define TSTAGE (4 * TTEN)      // Ah | Al | Wh | Wl       = 40960 B
#define GSMEM  (2 * TSTAGE)    // double buffered         = 81920 B

__global__ __launch_bounds__(256, 1)
void gemm_bf16_split(const __nv_bfloat16* __restrict__ Ah,
                     const __nv_bfloat16* __restrict__ Al,
                     const __nv_bfloat16* __restrict__ Wh,
                     const __nv_bfloat16* __restrict__ Wl,
                     const float* __restrict__ bias,
                     float* __restrict__ out, int mode)
{
    extern __shared__ __align__(128) char sm[];
    uint32_t sbase = smem_u32(sm);
    const int tid = threadIdx.x, wid = tid >> 5, lid = tid & 31;
    const int n0 = blockIdx.x * 128, m0 = blockIdx.y * 128;
    const int wm = wid & 3, wn = wid >> 2;

    const char* src[4] = { (const char*)(Ah + (size_t)m0 * En),
                           (const char*)(Al + (size_t)m0 * En),
                           (const char*)(Wh + (size_t)n0 * En),
                           (const char*)(Wl + (size_t)n0 * En) };

    // Per-thread fill geometry: 2048 16B chunks per stage, 8 per thread.
    auto fill = [&](int buf, int ks) {
        uint32_t st = sbase + buf * TSTAGE;
        size_t koff = (size_t)ks * (KC * 2);   // byte offset into the K dim
#pragma unroll
        for (int it = 0; it < 8; it++) {
            int idx = tid + it * 256;          // 0..2047
            int t = idx >> 9;                  // tensor 0..3
            int rc = idx & 511;                // chunk within tensor
            int r = rc >> 2, c = rc & 3;       // row 0..127, 16B col 0..3
            CP16(st + t * TTEN + r * TROW + c * 16,
                 src[t] + koff + (size_t)r * 2048 + c * 16);
        }
        CP_COMMIT();
    };

    float acc[2][8][4];
#pragma unroll
    for (int mi = 0; mi < 2; mi++)
#pragma unroll
        for (int nj = 0; nj < 8; nj++)
#pragma unroll
            for (int q = 0; q < 4; q++) acc[mi][nj][q] = 0.f;

    fill(0, 0);

    const int NST = En / KC;   // 32 stages
    for (int s = 0; s < NST; s++) {
        int buf = s & 1;
        if (s + 1 < NST) { fill(buf ^ 1, s + 1); CP_WAIT1(); }
        else            { CP_WAIT0(); }
        __syncthreads();

        uint32_t Ab  = sbase + buf * TSTAGE;
        uint32_t Alb = Ab + TTEN;
        uint32_t Wb  = Ab + 2 * TTEN;
        uint32_t Wlb = Ab + 3 * TTEN;

#pragma unroll
        for (int kb = 0; kb < KC; kb += 16) {
            // ---- A fragments (hi & lo), 2 m-tiles of 16x16 ----
            uint32_t ah[2][4], al[2][4];
            {
                int arow = wm * 32 + (lid & 7) + ((lid >> 3) & 1) * 8;
                int acol = kb + (lid >> 4) * 8;
                uint32_t aoff = arow * TROW + acol * 2;
#pragma unroll
                for (int mi = 0; mi < 2; mi++) {
                    LDSM4(ah[mi][0], ah[mi][1], ah[mi][2], ah[mi][3],
                          Ab + mi * (16 * TROW) + aoff);
                    LDSM4(al[mi][0], al[mi][1], al[mi][2], al[mi][3],
                          Alb + mi * (16 * TROW) + aoff);
                }
            }
            // ---- B fragments (hi & lo), 8 n-tiles of 8x16 (pairs via x4) ----
            uint32_t bh[8][2], bl[8][2];
            {
                int brow = wn * 64 + (lid & 7) + (lid >> 4) * 8;
                int bcol = kb + ((lid >> 3) & 1) * 8;
                uint32_t boff = brow * TROW + bcol * 2;
#pragma unroll
                for (int p = 0; p < 4; p++) {
                    uint32_t r0, r1, r2, r3;
                    LDSM4(r0, r1, r2, r3, Wb + p * (16 * TROW) + boff);
                    bh[p * 2][0] = r0; bh[p * 2][1] = r1;
                    bh[p * 2 + 1][0] = r2; bh[p * 2 + 1][1] = r3;
                    LDSM4(r0, r1, r2, r3, Wlb + p * (16 * TROW) + boff);
                    bl[p * 2][0] = r0; bl[p * 2][1] = r1;
                    bl[p * 2 + 1][0] = r2; bl[p * 2 + 1][1] = r3;
                }
            }
            // ---- 3-term MMA ----
#pragma unroll
            for (int mi = 0; mi < 2; mi++)
#pragma unroll
                for (int nj = 0; nj < 8; nj++) {
                    mma16816(acc[mi][nj], ah[mi], bh[nj]);
                    mma16816(acc[mi][nj], ah[mi], bl[nj]);
                    mma16816(acc[mi][nj], al[mi], bh[nj]);
                }
        }
        __syncthreads();
    }

    // ---- Epilogue: fragment layout -> gmem (float2 stores), + bias ----
    int m_base = m0 + wm * 32;
    int n_base = n0 + wn * 64;
    int rsub = lid >> 2, csub = (lid & 3) * 2;
#pragma unroll
    for (int mi = 0; mi < 2; mi++) {
#pragma unroll
        for (int nj = 0; nj < 8; nj++) {
            int cc = n_base + nj * 8 + csub;
            float bx = bias[cc], by = bias[cc + 1];
#pragma unroll
            for (int half = 0; half < 2; half++) {
                int m = m_base + mi * 16 + rsub + half * 8;
                float2 v;
                v.x = acc[mi][nj][half * 2 + 0] + bx;
                v.y = acc[mi][nj][half * 2 + 1] + by;
                if (mode == 0) {
                    *(float2*)&out[(size_t)m * En + cc] = v;
                } else {
                    int h = cc >> 6, d = cc & 63;
                    int b = m >> 11, ss = m & 2047;
                    *(float2*)&out[(((size_t)b * Hn + h) * Sn + ss) * Dn + d] = v;
                }
            }
        }
    }
}

// ---------------------------------------------------------------------------
// Flash-style causal attention, pass 1 (unchanged)
// ---------------------------------------------------------------------------
__global__ __launch_bounds__(256, 2)
void attn_pass1(const float* __restrict__ Q, const float* __restrict__ Kg,
                const float* __restrict__ Vg, float* __restrict__ ctx,
                float* __restrict__ gm, float* __restrict__ gl)
{
    extern __shared__ float smf[];
    float* Qs  = smf;
    float* Kts = smf + 64 * TP;
    float* Vs  = smf + 2 * 64 * TP;
    float* Ss  = smf + 3 * 64 * TP;

    int qt = blockIdx.x, bh = blockIdx.y;
    int q0 = qt * 64;
    const float* Qb = Q  + (size_t)bh * Sn * Dn;
    const float* Kb = Kg + (size_t)bh * Sn * Dn;
    const float* Vb = Vg + (size_t)bh * Sn * Dn;
    int tid = threadIdx.x, ty = tid >> 4, tx = tid & 15;

    for (int idx = tid; idx < 64 * 16; idx += 256) {
        int r = idx >> 4, c4 = (idx & 15) << 2;
        *(float4*)&Qs[r * TP + c4] = *(const float4*)&Qb[(size_t)(q0 + r) * Dn + c4];
    }

    float m_i[4], l_i[4], o[4][4];
#pragma unroll
    for (int i = 0; i < 4; i++) {
        m_i[i] = -1e30f; l_i[i] = 0.f;
#pragma unroll
        for (int j = 0; j < 4; j++) o[i][j] = 0.f;
    }

    for (int kt = 0; kt <= qt; kt++) {
        __syncthreads();
        for (int idx = tid; idx < 64 * 16; idx += 256) {
            int c = idx >> 4, d4 = (idx & 15) << 2;
            float4 kv = *(const float4*)&Kb[(size_t)(kt * 64 + c) * Dn + d4];
            Kts[(d4 + 0) * TP + c] = kv.x;
            Kts[(d4 + 1) * TP + c] = kv.y;
            Kts[(d4 + 2) * TP + c] = kv.z;
            Kts[(d4 + 3) * TP + c] = kv.w;
            *(float4*)&Vs[c * TP + d4] = *(const float4*)&Vb[(size_t)(kt * 64 + c) * Dn + d4];
        }
        __syncthreads();

        float s[4][4];
#pragma unroll
        for (int i = 0; i < 4; i++)
#pragma unroll
            for (int j = 0; j < 4; j++) s[i][j] = 0.f;

#pragma unroll 16
        for (int d = 0; d < 64; d++) {
            float4 kv = *(const float4*)&Kts[d * TP + (tx << 2)];
#pragma unroll
            for (int i = 0; i < 4; i++) {
                float qv = Qs[(ty * 4 + i) * TP + d];
                s[i][0] = fmaf(qv, kv.x, s[i][0]);
                s[i][1] = fmaf(qv, kv.y, s[i][1]);
                s[i][2] = fmaf(qv, kv.z, s[i][2]);
                s[i][3] = fmaf(qv, kv.w, s[i][3]);
            }
        }

        const float scale = 0.125f;
        if (kt == qt) {
#pragma unroll
            for (int i = 0; i < 4; i++) {
                int rr = q0 + ty * 4 + i;
#pragma unroll
                for (int j = 0; j < 4; j++) {
                    int cc = kt * 64 + (tx << 2) + j;
                    s[i][j] = (cc <= rr) ? s[i][j] * scale : -1e9f;
                }
            }
        } else {
#pragma unroll
            for (int i = 0; i < 4; i++)
#pragma unroll
                for (int j = 0; j < 4; j++) s[i][j] *= scale;
        }

#pragma unroll
        for (int i = 0; i < 4; i++) {
            float tmax = fmaxf(fmaxf(s[i][0], s[i][1]), fmaxf(s[i][2], s[i][3]));
#pragma unroll
            for (int off = 8; off > 0; off >>= 1)
                tmax = fmaxf(tmax, __shfl_xor_sync(0xffffffffu, tmax, off));
            float mnew = fmaxf(m_i[i], tmax);
            float fac  = __expf(m_i[i] - mnew);
            float rs = 0.f;
#pragma unroll
            for (int j = 0; j < 4; j++) { s[i][j] = __expf(s[i][j] - mnew); rs += s[i][j]; }
#pragma unroll
            for (int off = 8; off > 0; off >>= 1)
                rs += __shfl_xor_sync(0xffffffffu, rs, off);
            l_i[i] = l_i[i] * fac + rs;
            m_i[i] = mnew;
#pragma unroll
            for (int j = 0; j < 4; j++) o[i][j] *= fac;
        }

#pragma unroll
        for (int i = 0; i < 4; i++)
            *(float4*)&Ss[(ty * 4 + i) * TP + (tx << 2)] =
                make_float4(s[i][0], s[i][1], s[i][2], s[i][3]);
        __syncthreads();

#pragma unroll 16
        for (int c = 0; c < 64; c++) {
            float4 vv = *(const float4*)&Vs[c * TP + (tx << 2)];
#pragma unroll
            for (int i = 0; i < 4; i++) {
                float pv = Ss[(ty * 4 + i) * TP + c];
                o[i][0] = fmaf(pv, vv.x, o[i][0]);
                o[i][1] = fmaf(pv, vv.y, o[i][1]);
                o[i][2] = fmaf(pv, vv.z, o[i][2]);
                o[i][3] = fmaf(pv, vv.w, o[i][3]);
            }
        }
    }

    int b = bh >> 4, h = bh & 15;
#pragma unroll
    for (int i = 0; i < 4; i++) {
        float inv = 1.f / l_i[i];
        int sg = q0 + ty * 4 + i;
        float4 ov = make_float4(o[i][0] * inv, o[i][1] * inv, o[i][2] * inv, o[i][3] * inv);
        *(float4*)&ctx[((size_t)b * Sn + sg) * En + h * Dn + (tx << 2)] = ov;
        if (tx == 0) {
            gm[bh * Sn + sg] = m_i[i];
            gl[bh * Sn + sg] = l_i[i];
        }
    }
}

// ---------------------------------------------------------------------------
// Pass 2: recompute scores per tile and write attn probabilities (unchanged).
// ---------------------------------------------------------------------------
__global__ __launch_bounds__(256)
void attn_write(const float* __restrict__ Q, const float* __restrict__ Kg,
                const float* __restrict__ gm, const float* __restrict__ gl,
                float* __restrict__ attn)
{
    __shared__ float Qs[64 * TP];
    __shared__ float Kts[64 * TP];
    int kt = blockIdx.x, qt = blockIdx.y, bh = blockIdx.z;
    int tid = threadIdx.x, ty = tid >> 4, tx = tid & 15;
    int q0 = qt * 64;
    float* arow = attn + (size_t)bh * Sn * Sn;

    if (kt > qt) {
        float4 z = make_float4(0.f, 0.f, 0.f, 0.f);
        for (int idx = tid; idx < 64 * 16; idx += 256) {
            int r = idx >> 4, c4 = (idx & 15) << 2;
            *(float4*)&arow[(size_t)(q0 + r) * Sn + kt * 64 + c4] = z;
        }
        return;
    }

    const float* Qb = Q  + (size_t)bh * Sn * Dn;
    const float* Kb = Kg + (size_t)bh * Sn * Dn;
    for (int idx = tid; idx < 64 * 16; idx += 256) {
        int r = idx >> 4, c4 = (idx & 15) << 2;
        *(float4*)&Qs[r * TP + c4] = *(const float4*)&Qb[(size_t)(q0 + r) * Dn + c4];
        int c = r, d4 = c4;
        float4 kv = *(const float4*)&Kb[(size_t)(kt * 64 + c) * Dn + d4];
        Kts[(d4 + 0) * TP + c] = kv.x;
        Kts[(d4 + 1) * TP + c] = kv.y;
        Kts[(d4 + 2) * TP + c] = kv.z;
        Kts[(d4 + 3) * TP + c] = kv.w;
    }
    __syncthreads();

    float s[4][4];
#pragma unroll
    for (int i = 0; i < 4; i++)
#pragma unroll
        for (int j = 0; j < 4; j++) s[i][j] = 0.f;

#pragma unroll 16
    for (int d = 0; d < 64; d++) {
        float4 kv = *(const float4*)&Kts[d * TP + (tx << 2)];
#pragma unroll
        for (int i = 0; i < 4; i++) {
            float qv = Qs[(ty * 4 + i) * TP + d];
            s[i][0] = fmaf(qv, kv.x, s[i][0]);
            s[i][1] = fmaf(qv, kv.y, s[i][1]);
            s[i][2] = fmaf(qv, kv.z, s[i][2]);
            s[i][3] = fmaf(qv, kv.w, s[i][3]);
        }
    }

    const float scale = 0.125f;
#pragma unroll
    for (int i = 0; i < 4; i++) {
        int rr = q0 + ty * 4 + i;
        float mr  = gm[bh * Sn + rr];
        float inv = 1.f / gl[bh * Sn + rr];
        float4 p;
        float* pp = (float*)&p;
#pragma unroll
        for (int j = 0; j < 4; j++) {
            int cc = kt * 64 + (tx << 2) + j;
            float sv = (kt == qt && cc > rr) ? -1e9f : s[i][j] * scale;
            pp[j] = __expf(sv - mr) * inv;
        }
        *(float4*)&arow[(size_t)rr * Sn + kt * 64 + (tx << 2)] = p;
    }
}

// ---------------------------------------------------------------------------
extern "C" void kernel_launch(void* const* d_in, const int* in_sizes, int n_in,
                              void* d_out, int out_size)
{
    const float* query = (const float*)d_in[0];
    const float* key   = (const float*)d_in[1];
    const float* value = (const float*)d_in[2];
    // d_in[3] = mask (bool, causal tril) — applied analytically
    const float* Wq = (const float*)d_in[4];
    const float* bq = (const float*)d_in[5];
    const float* Wk = (const float*)d_in[6];
    const float* bk = (const float*)d_in[7];
    const float* Wv = (const float*)d_in[8];
    const float* bv = (const float*)d_in[9];
    const float* Wo = (const float*)d_in[10];
    const float* bo = (const float*)d_in[11];

    float *pq, *pk, *pv, *pctx, *pm, *pl;
    cudaGetSymbolAddress((void**)&pq,   g_q);
    cudaGetSymbolAddress((void**)&pk,   g_k);
    cudaGetSymbolAddress((void**)&pv,   g_v);
    cudaGetSymbolAddress((void**)&pctx, g_ctx);
    cudaGetSymbolAddress((void**)&pm,   g_m);
    cudaGetSymbolAddress((void**)&pl,   g_l);
    __nv_bfloat16 *pAh, *pAl, *pWh, *pWl;
    cudaGetSymbolAddress((void**)&pAh, g_Ahi);
    cudaGetSymbolAddress((void**)&pAl, g_Alo);
    cudaGetSymbolAddress((void**)&pWh, g_Whi);
    cudaGetSymbolAddress((void**)&pWl, g_Wlo);

    static bool attr_set = false;
    if (!attr_set) {
        cudaFuncSetAttribute(gemm_bf16_split,
                             cudaFuncAttributeMaxDynamicSharedMemorySize, GSMEM);
        cudaFuncSetAttribute(attn_pass1,
                             cudaFuncAttributeMaxDynamicSharedMemorySize,
                             (int)((size_t)4 * 64 * TP * sizeof(float)));
        attr_set = true;
    }

    const int NA4 = (Mn * En) / 4;   // A-side float4 count
    const int NW4 = (En * En) / 4;   // W-side float4 count
    dim3 gg(En / 128, Mn / 128);     // (8, 32)

    auto run_gemm = [&](const float* A, const float* W, const float* bias,
                        float* outp, int mode) {
        split_bf16<<<(NA4 + 255) / 256, 256>>>((const float4*)A,
                                               (__nv_bfloat162*)pAh,
                                               (__nv_bfloat162*)pAl, NA4);
        split_bf16<<<(NW4 + 255) / 256, 256>>>((const float4*)W,
                                               (__nv_bfloat162*)pWh,
                                               (__nv_bfloat162*)pWl, NW4);
        gemm_bf16_split<<<gg, 256, GSMEM>>>(pAh, pAl, pWh, pWl, bias, outp, mode);
    };

    run_gemm(query, Wq, bq, pq, 1);
    run_gemm(key,   Wk, bk, pk, 1);
    run_gemm(value, Wv, bv, pv, 1);

    size_t smem1 = (size_t)4 * 64 * TP * sizeof(float);  // 69632 B
    attn_pass1<<<dim3(Sn / 64, BHn), 256, smem1>>>(pq, pk, pv, pctx, pm, pl);

    const size_t OUT_ELEMS  = (size_t)Bn * Sn * En;       //   4,194,304
    const size_t ATTN_ELEMS = (size_t)BHn * Sn * Sn;      // 134,217,728
    float* outp  = (float*)d_out;
    float* attnp = nullptr;
    if ((size_t)out_size >= OUT_ELEMS + ATTN_ELEMS) {
        attnp = outp + OUT_ELEMS;                 // tuple (out, attn) concatenated
    } else if ((size_t)out_size == ATTN_ELEMS) {
        attnp = outp; outp = nullptr;             // attn only
    }

    if (attnp)
        attn_write<<<dim3(Sn / 64, Sn / 64, BHn), 256>>>(pq, pk, pm, pl, attnp);
    if (outp)
        run_gemm(pctx, Wo, bo, outp, 0);
}

// round 4
// speedup vs baseline: 2.2362x; 1.6665x over previous
#include <cuda_runtime.h>
#include <cuda_bf16.h>
#include <math.h>
#include <stdint.h>

#define Bn 2
#define Sn 2048
#define En 1024
#define Hn 16
#define Dn 64
#define Mn (Bn*Sn)    // 4096
#define BHn (Bn*Hn)   // 32

// ---------------- scratch (device globals; no allocation allowed) ----------
__device__ __nv_bfloat16 g_qh[(size_t)BHn*Sn*Dn], g_ql[(size_t)BHn*Sn*Dn];
__device__ __nv_bfloat16 g_kh[(size_t)BHn*Sn*Dn], g_kl[(size_t)BHn*Sn*Dn];
__device__ __nv_bfloat16 g_vh[(size_t)BHn*Sn*Dn], g_vl[(size_t)BHn*Sn*Dn];
__device__ __nv_bfloat16 g_ctxh[(size_t)Mn*En],   g_ctxl[(size_t)Mn*En];
__device__ __nv_bfloat16 g_Ahi[(size_t)Mn*En],    g_Alo[(size_t)Mn*En];
__device__ __nv_bfloat16 g_Whi[(size_t)En*En],    g_Wlo[(size_t)En*En];
__device__ float g_m[BHn*Sn];
__device__ float g_l[BHn*Sn];

// ---------------- PTX helpers (base-target only) ---------------------------
__device__ __forceinline__ uint32_t smem_u32(const void* p) {
    uint32_t a;
    asm("{ .reg .u64 t; cvta.to.shared.u64 t, %1; cvt.u32.u64 %0, t; }"
        : "=r"(a) : "l"(p));
    return a;
}
#define CP16(dst, src) \
    asm volatile("cp.async.cg.shared.global [%0], [%1], 16;\n" :: "r"(dst), "l"(src))
#define CP_COMMIT() asm volatile("cp.async.commit_group;\n" ::)
#define CP_WAIT0()  asm volatile("cp.async.wait_group 0;\n" ::)
#define CP_WAIT1()  asm volatile("cp.async.wait_group 1;\n" ::)
#define LDSM4(R0, R1, R2, R3, A) \
    asm volatile("ldmatrix.sync.aligned.m8n8.x4.shared.b16 {%0,%1,%2,%3}, [%4];" \
                 : "=r"(R0), "=r"(R1), "=r"(R2), "=r"(R3) : "r"(A))
#define LDSM4T(R0, R1, R2, R3, A) \
    asm volatile("ldmatrix.sync.aligned.m8n8.x4.trans.shared.b16 {%0,%1,%2,%3}, [%4];" \
                 : "=r"(R0), "=r"(R1), "=r"(R2), "=r"(R3) : "r"(A))

__device__ __forceinline__ void mma16816(float* c, const uint32_t* a, const uint32_t* b) {
    asm volatile(
        "mma.sync.aligned.m16n8k16.row.col.f32.bf16.bf16.f32 "
        "{%0,%1,%2,%3}, {%4,%5,%6,%7}, {%8,%9}, {%0,%1,%2,%3};"
        : "+f"(c[0]), "+f"(c[1]), "+f"(c[2]), "+f"(c[3])
        : "r"(a[0]), "r"(a[1]), "r"(a[2]), "r"(a[3]), "r"(b[0]), "r"(b[1]));
}

// ===========================================================================
// Split fp32 -> (hi, lo) bf16 pair.
// ===========================================================================
__global__ void split_bf16(const float4* __restrict__ x,
                           __nv_bfloat162* __restrict__ hi,
                           __nv_bfloat162* __restrict__ lo, int n4)
{
    int i = blockIdx.x * blockDim.x + threadIdx.x;
    if (i >= n4) return;
    float4 v = x[i];
    __nv_bfloat16 h0 = __float2bfloat16(v.x), h1 = __float2bfloat16(v.y);
    __nv_bfloat16 h2 = __float2bfloat16(v.z), h3 = __float2bfloat16(v.w);
    hi[i * 2 + 0] = __halves2bfloat162(h0, h1);
    hi[i * 2 + 1] = __halves2bfloat162(h2, h3);
    lo[i * 2 + 0] = __halves2bfloat162(
        __float2bfloat16(v.x - __bfloat162float(h0)),
        __float2bfloat16(v.y - __bfloat162float(h1)));
    lo[i * 2 + 1] = __halves2bfloat162(
        __float2bfloat16(v.z - __bfloat162float(h2)),
        __float2bfloat16(v.w - __bfloat162float(h3)));
}

// ===========================================================================
// Tensor-core GEMM: C = A * W^T + bias, 3-term bf16 split.
// mode 0: fp32 out row-major [M, En]
// mode 1: bf16 hi/lo out in head-split layout [B, H, S, D]
// ===========================================================================
#define KC     32
#define TROW   80
#define TTEN   (128 * TROW)
#define TSTAGE (4 * TTEN)
#define GSMEM  (2 * TSTAGE)

__global__ __launch_bounds__(256, 1)
void gemm_bf16_split(const __nv_bfloat16* __restrict__ Ah,
                     const __nv_bfloat16* __restrict__ Al,
                     const __nv_bfloat16* __restrict__ Wh,
                     const __nv_bfloat16* __restrict__ Wl,
                     const float* __restrict__ bias,
                     float* __restrict__ out,
                     __nv_bfloat16* __restrict__ oH,
                     __nv_bfloat16* __restrict__ oL, int mode)
{
    extern __shared__ __align__(128) char sm[];
    uint32_t sbase = smem_u32(sm);
    const int tid = threadIdx.x, wid = tid >> 5, lid = tid & 31;
    const int n0 = blockIdx.x * 128, m0 = blockIdx.y * 128;
    const int wm = wid & 3, wn = wid >> 2;

    const char* src[4] = { (const char*)(Ah + (size_t)m0 * En),
                           (const char*)(Al + (size_t)m0 * En),
                           (const char*)(Wh + (size_t)n0 * En),
                           (const char*)(Wl + (size_t)n0 * En) };

    auto fill = [&](int buf, int ks) {
        uint32_t st = sbase + buf * TSTAGE;
        size_t koff = (size_t)ks * (KC * 2);
#pragma unroll
        for (int it = 0; it < 8; it++) {
            int idx = tid + it * 256;
            int t = idx >> 9;
            int rc = idx & 511;
            int r = rc >> 2, c = rc & 3;
            CP16(st + t * TTEN + r * TROW + c * 16,
                 src[t] + koff + (size_t)r * 2048 + c * 16);
        }
        CP_COMMIT();
    };

    float acc[2][8][4];
#pragma unroll
    for (int mi = 0; mi < 2; mi++)
#pragma unroll
        for (int nj = 0; nj < 8; nj++)
#pragma unroll
            for (int q = 0; q < 4; q++) acc[mi][nj][q] = 0.f;

    fill(0, 0);

    const int NST = En / KC;
    for (int s = 0; s < NST; s++) {
        int buf = s & 1;
        if (s + 1 < NST) { fill(buf ^ 1, s + 1); CP_WAIT1(); }
        else            { CP_WAIT0(); }
        __syncthreads();

        uint32_t Ab  = sbase + buf * TSTAGE;
        uint32_t Alb = Ab + TTEN;
        uint32_t Wb  = Ab + 2 * TTEN;
        uint32_t Wlb = Ab + 3 * TTEN;

#pragma unroll
        for (int kb = 0; kb < KC; kb += 16) {
            uint32_t ah[2][4], al[2][4];
            {
                int arow = wm * 32 + (lid & 7) + ((lid >> 3) & 1) * 8;
                int acol = kb + (lid >> 4) * 8;
                uint32_t aoff = arow * TROW + acol * 2;
#pragma unroll
                for (int mi = 0; mi < 2; mi++) {
                    LDSM4(ah[mi][0], ah[mi][1], ah[mi][2], ah[mi][3],
                          Ab + mi * (16 * TROW) + aoff);
                    LDSM4(al[mi][0], al[mi][1], al[mi][2], al[mi][3],
                          Alb + mi * (16 * TROW) + aoff);
                }
            }
            uint32_t bh[8][2], bl[8][2];
            {
                int brow = wn * 64 + (lid & 7) + (lid >> 4) * 8;
                int bcol = kb + ((lid >> 3) & 1) * 8;
                uint32_t boff = brow * TROW + bcol * 2;
#pragma unroll
                for (int p = 0; p < 4; p++) {
                    uint32_t r0, r1, r2, r3;
                    LDSM4(r0, r1, r2, r3, Wb + p * (16 * TROW) + boff);
                    bh[p * 2][0] = r0; bh[p * 2][1] = r1;
                    bh[p * 2 + 1][0] = r2; bh[p * 2 + 1][1] = r3;
                    LDSM4(r0, r1, r2, r3, Wlb + p * (16 * TROW) + boff);
                    bl[p * 2][0] = r0; bl[p * 2][1] = r1;
                    bl[p * 2 + 1][0] = r2; bl[p * 2 + 1][1] = r3;
                }
            }
#pragma unroll
            for (int mi = 0; mi < 2; mi++)
#pragma unroll
                for (int nj = 0; nj < 8; nj++) {
                    mma16816(acc[mi][nj], ah[mi], bh[nj]);
                    mma16816(acc[mi][nj], ah[mi], bl[nj]);
                    mma16816(acc[mi][nj], al[mi], bh[nj]);
                }
        }
        __syncthreads();
    }

    int m_base = m0 + wm * 32;
    int n_base = n0 + wn * 64;
    int rsub = lid >> 2, csub = (lid & 3) * 2;
#pragma unroll
    for (int mi = 0; mi < 2; mi++) {
#pragma unroll
        for (int nj = 0; nj < 8; nj++) {
            int cc = n_base + nj * 8 + csub;
            float bx = bias[cc], by = bias[cc + 1];
#pragma unroll
            for (int half = 0; half < 2; half++) {
                int m = m_base + mi * 16 + rsub + half * 8;
                float vx = acc[mi][nj][half * 2 + 0] + bx;
                float vy = acc[mi][nj][half * 2 + 1] + by;
                if (mode == 0) {
                    float2 v; v.x = vx; v.y = vy;
                    *(float2*)&out[(size_t)m * En + cc] = v;
                } else {
                    int h = cc >> 6, d = cc & 63;
                    int b = m >> 11, ss = m & 2047;
                    size_t idx = (((size_t)b * Hn + h) * Sn + ss) * Dn + d;
                    __nv_bfloat162 hi = __floats2bfloat162_rn(vx, vy);
                    __nv_bfloat162 lo = __floats2bfloat162_rn(
                        vx - __bfloat162float(hi.x), vy - __bfloat162float(hi.y));
                    *(uint32_t*)&oH[idx] = *(uint32_t*)&hi;
                    *(uint32_t*)&oL[idx] = *(uint32_t*)&lo;
                }
            }
        }
    }
}

// ===========================================================================
// Flash pass 1 on tensor cores. CTA: 128 q-rows, 8 warps (16 q-rows each),
// 64-key tiles double-buffered. 3-term split for QK and PV.
// Outputs ctx hi/lo bf16 [B,S,E] and per-row m,l.
// ===========================================================================
#define KR 144               // smem row stride (bytes) for 64-bf16 rows
#define QSM (128*KR)         // 18432
#define KVT (64*KR)          // 9216
#define KVSTG (4*KVT)        // 36864
#define P1SMEM (2*QSM + 2*KVSTG)   // 110592

__global__ __launch_bounds__(256, 1)
void attn_pass1(const __nv_bfloat16* __restrict__ qh, const __nv_bfloat16* __restrict__ ql,
                const __nv_bfloat16* __restrict__ kh, const __nv_bfloat16* __restrict__ kl,
                const __nv_bfloat16* __restrict__ vh, const __nv_bfloat16* __restrict__ vl,
                __nv_bfloat16* __restrict__ ctxh, __nv_bfloat16* __restrict__ ctxl,
                float* __restrict__ gm, float* __restrict__ gl)
{
    extern __shared__ __align__(128) char sm[];
    uint32_t sb = smem_u32(sm);
    const int tid = threadIdx.x, wid = tid >> 5, lid = tid & 31;
    const int qt = (gridDim.x - 1) - blockIdx.x;   // big tiles first
    const int bh = blockIdx.y;
    const int q0 = qt * 128;
    const size_t hbase = (size_t)bh * Sn * Dn;

    const char* gq[2]  = { (const char*)(qh + hbase + (size_t)q0 * Dn),
                           (const char*)(ql + hbase + (size_t)q0 * Dn) };
    const char* gkv[4] = { (const char*)(kh + hbase), (const char*)(kl + hbase),
                           (const char*)(vh + hbase), (const char*)(vl + hbase) };

    uint32_t Qb = sb, KVb = sb + 2 * QSM;

    // Q fill (no commit; joins first KV group)
#pragma unroll
    for (int i = 0; i < 8; i++) {
        int idx = tid + i * 256;          // 0..2047
        int t = idx >> 10, rc = idx & 1023, r = rc >> 3, c = rc & 7;
        CP16(Qb + t * QSM + r * KR + c * 16, gq[t] + (size_t)r * 128 + c * 16);
    }
    auto fillKV = [&](int buf, int kt) {
        uint32_t st = KVb + buf * KVSTG;
        size_t gof = (size_t)kt * 64 * 128;
#pragma unroll
        for (int i = 0; i < 8; i++) {
            int idx = tid + i * 256;      // 0..2047
            int t = idx >> 9, rc = idx & 511, r = rc >> 3, c = rc & 7;
            CP16(st + t * KVT + r * KR + c * 16, gkv[t] + gof + (size_t)r * 128 + c * 16);
        }
        CP_COMMIT();
    };
    fillKV(0, 0);

    uint32_t qfh[4][4], qfl[4][4];
    float o[8][4];
#pragma unroll
    for (int nj = 0; nj < 8; nj++)
#pragma unroll
        for (int e = 0; e < 4; e++) o[nj][e] = 0.f;
    float mrow[2] = {-1e30f, -1e30f}, lrow[2] = {0.f, 0.f};

    const int ktmax = 2 * qt + 1;
    for (int kt = 0; kt <= ktmax; kt++) {
        int buf = kt & 1;
        if (kt < ktmax) { fillKV(buf ^ 1, kt + 1); CP_WAIT1(); }
        else            { CP_WAIT0(); }
        __syncthreads();
        if (kt == 0) {
            int ar = wid * 16 + (lid & 7) + ((lid >> 3) & 1) * 8;
#pragma unroll
            for (int t = 0; t < 4; t++) {
                uint32_t off = Qb + ar * KR + t * 32 + (lid >> 4) * 16;
                LDSM4(qfh[t][0], qfh[t][1], qfh[t][2], qfh[t][3], off);
                LDSM4(qfl[t][0], qfl[t][1], qfl[t][2], qfl[t][3], off + QSM);
            }
        }
        uint32_t Kh_ = KVb + buf * KVSTG;
        uint32_t Vh_ = Kh_ + 2 * KVT;

        // ---- S = Q K^T (3-term) ----
        float sf[8][4];
#pragma unroll
        for (int nj = 0; nj < 8; nj++)
#pragma unroll
            for (int e = 0; e < 4; e++) sf[nj][e] = 0.f;

        int br = (lid & 7) + (lid >> 4) * 8;
#pragma unroll
        for (int t = 0; t < 4; t++) {
            int bc = t * 32 + ((lid >> 3) & 1) * 16;
#pragma unroll
            for (int p = 0; p < 4; p++) {
                uint32_t b0, b1, b2, b3, c0, c1, c2, c3;
                uint32_t ad = Kh_ + (p * 16 + br) * KR + bc;
                LDSM4(b0, b1, b2, b3, ad);
                LDSM4(c0, c1, c2, c3, ad + KVT);
                uint32_t Bh0[2] = {b0, b1}, Bh1[2] = {b2, b3};
                uint32_t Bl0[2] = {c0, c1}, Bl1[2] = {c2, c3};
                mma16816(sf[2*p],   qfh[t], Bh0);
                mma16816(sf[2*p],   qfh[t], Bl0);
                mma16816(sf[2*p],   qfl[t], Bh0);
                mma16816(sf[2*p+1], qfh[t], Bh1);
                mma16816(sf[2*p+1], qfh[t], Bl1);
                mma16816(sf[2*p+1], qfl[t], Bh1);
            }
        }

        // ---- online softmax ----
        const float scale = 0.125f;
        bool domask = (kt * 64 + 63) > (q0 + wid * 16);
        float tmax[2] = {-1e30f, -1e30f};
#pragma unroll
        for (int nj = 0; nj < 8; nj++)
#pragma unroll
            for (int e = 0; e < 4; e++) {
                float s = sf[nj][e] * scale;
                if (domask) {
                    int kc = kt * 64 + nj * 8 + 2 * (lid & 3) + (e & 1);
                    int qr = q0 + wid * 16 + (lid >> 2) + 8 * (e >> 1);
                    if (kc > qr) s = -1e9f;
                }
                sf[nj][e] = s;
                tmax[e >> 1] = fmaxf(tmax[e >> 1], s);
            }
#pragma unroll
        for (int h = 0; h < 2; h++) {
            tmax[h] = fmaxf(tmax[h], __shfl_xor_sync(0xffffffffu, tmax[h], 1));
            tmax[h] = fmaxf(tmax[h], __shfl_xor_sync(0xffffffffu, tmax[h], 2));
        }
        float fac[2], rsum[2] = {0.f, 0.f};
#pragma unroll
        for (int h = 0; h < 2; h++) {
            float mn = fmaxf(mrow[h], tmax[h]);
            fac[h] = __expf(mrow[h] - mn);
            mrow[h] = mn;
        }
#pragma unroll
        for (int nj = 0; nj < 8; nj++)
#pragma unroll
            for (int e = 0; e < 4; e++) {
                float p = __expf(sf[nj][e] - mrow[e >> 1]);
                sf[nj][e] = p;
                rsum[e >> 1] += p;
            }
#pragma unroll
        for (int h = 0; h < 2; h++) {
            rsum[h] += __shfl_xor_sync(0xffffffffu, rsum[h], 1);
            rsum[h] += __shfl_xor_sync(0xffffffffu, rsum[h], 2);
            lrow[h] = lrow[h] * fac[h] + rsum[h];
        }
#pragma unroll
        for (int nj = 0; nj < 8; nj++)
#pragma unroll
            for (int e = 0; e < 4; e++) o[nj][e] *= fac[e >> 1];

        // ---- O += P V (3-term) ----
        int vr = (lid & 7) + ((lid >> 3) & 1) * 8;
        int vc = (lid >> 4) * 16;
#pragma unroll
        for (int t = 0; t < 4; t++) {
            uint32_t pha[4], pla[4];
#pragma unroll
            for (int u = 0; u < 2; u++) {
                float x0 = sf[2*t+u][0], x1 = sf[2*t+u][1];
                float x2 = sf[2*t+u][2], x3 = sf[2*t+u][3];
                __nv_bfloat162 h01 = __floats2bfloat162_rn(x0, x1);
                __nv_bfloat162 h23 = __floats2bfloat162_rn(x2, x3);
                pha[2*u+0] = *(uint32_t*)&h01;
                pha[2*u+1] = *(uint32_t*)&h23;
                __nv_bfloat162 l01 = __floats2bfloat162_rn(
                    x0 - __bfloat162float(h01.x), x1 - __bfloat162float(h01.y));
                __nv_bfloat162 l23 = __floats2bfloat162_rn(
                    x2 - __bfloat162float(h23.x), x3 - __bfloat162float(h23.y));
                pla[2*u+0] = *(uint32_t*)&l01;
                pla[2*u+1] = *(uint32_t*)&l23;
            }
#pragma unroll
            for (int p = 0; p < 4; p++) {
                uint32_t b0, b1, b2, b3, c0, c1, c2, c3;
                uint32_t ad = Vh_ + (t * 16 + vr) * KR + p * 32 + vc;
                LDSM4T(b0, b1, b2, b3, ad);
                LDSM4T(c0, c1, c2, c3, ad + KVT);
                uint32_t Bh0[2] = {b0, b1}, Bh1[2] = {b2, b3};
                uint32_t Bl0[2] = {c0, c1}, Bl1[2] = {c2, c3};
                mma16816(o[2*p],   pha, Bh0);
                mma16816(o[2*p],   pha, Bl0);
                mma16816(o[2*p],   pla, Bh0);
                mma16816(o[2*p+1], pha, Bh1);
                mma16816(o[2*p+1], pha, Bl1);
                mma16816(o[2*p+1], pla, Bh1);
            }
        }
        __syncthreads();
    }

    // ---- epilogue: ctx hi/lo + m,l ----
    float invl[2] = {1.f / lrow[0], 1.f / lrow[1]};
    int b = bh >> 4, hh = bh & 15;
#pragma unroll
    for (int h = 0; h < 2; h++) {
        int r = q0 + wid * 16 + (lid >> 2) + 8 * h;
        size_t rowb = ((size_t)b * Sn + r) * En + hh * 64;
#pragma unroll
        for (int nj = 0; nj < 8; nj++) {
            int cc = nj * 8 + 2 * (lid & 3);
            float f0 = o[nj][2*h]   * invl[h];
            float f1 = o[nj][2*h+1] * invl[h];
            __nv_bfloat162 hi = __floats2bfloat162_rn(f0, f1);
            __nv_bfloat162 lo = __floats2bfloat162_rn(
                f0 - __bfloat162float(hi.x), f1 - __bfloat162float(hi.y));
            *(uint32_t*)&ctxh[rowb + cc] = *(uint32_t*)&hi;
            *(uint32_t*)&ctxl[rowb + cc] = *(uint32_t*)&lo;
        }
        if ((lid & 3) == 0) {
            gm[bh * Sn + r] = mrow[h];
            gl[bh * Sn + r] = lrow[h];
        }
    }
}

// ===========================================================================
// Pass 2: recompute P on tensor cores (3-term QK), write attn [BH,S,S].
// 128x128 tiles; kt>qt tiles write zeros.
// ===========================================================================
#define AWT   (128*KR)       // 18432
#define AWSMEM (4*AWT)       // 73728

__global__ __launch_bounds__(256, 1)
void attn_write(const __nv_bfloat16* __restrict__ qh, const __nv_bfloat16* __restrict__ ql,
                const __nv_bfloat16* __restrict__ kh, const __nv_bfloat16* __restrict__ kl,
                const float* __restrict__ gm, const float* __restrict__ gl,
                float* __restrict__ attn)
{
    const int kt = blockIdx.x, qt = blockIdx.y, bh = blockIdx.z;
    const int tid = threadIdx.x, wid = tid >> 5, lid = tid & 31;
    const int q0 = qt * 128, k0 = kt * 128;
    float* arow = attn + (size_t)bh * Sn * Sn;

    if (kt > qt) {
        float4 z = make_float4(0.f, 0.f, 0.f, 0.f);
#pragma unroll
        for (int i = 0; i < 16; i++) {
            int idx = tid + i * 256;          // 4096 float4
            int r = idx >> 5, c4 = (idx & 31) << 2;
            *(float4*)&arow[(size_t)(q0 + r) * Sn + k0 + c4] = z;
        }
        return;
    }

    extern __shared__ __align__(128) char sm[];
    uint32_t sb = smem_u32(sm);
    const size_t hbase = (size_t)bh * Sn * Dn;
    const char* gsrc[4] = { (const char*)(qh + hbase + (size_t)q0 * Dn),
                            (const char*)(ql + hbase + (size_t)q0 * Dn),
                            (const char*)(kh + hbase + (size_t)k0 * Dn),
                            (const char*)(kl + hbase + (size_t)k0 * Dn) };
#pragma unroll
    for (int i = 0; i < 16; i++) {
        int idx = tid + i * 256;              // 4096 chunks
        int t = idx >> 10, rc = idx & 1023, r = rc >> 3, c = rc & 7;
        CP16(sb + t * AWT + r * KR + c * 16, gsrc[t] + (size_t)r * 128 + c * 16);
    }
    CP_COMMIT(); CP_WAIT0();
    __syncthreads();

    uint32_t Qh_ = sb, Kh_ = sb + 2 * AWT;

    uint32_t qfh[4][4], qfl[4][4];
    int ar = wid * 16 + (lid & 7) + ((lid >> 3) & 1) * 8;
#pragma unroll
    for (int t = 0; t < 4; t++) {
        uint32_t off = Qh_ + ar * KR + t * 32 + (lid >> 4) * 16;
        LDSM4(qfh[t][0], qfh[t][1], qfh[t][2], qfh[t][3], off);
        LDSM4(qfl[t][0], qfl[t][1], qfl[t][2], qfl[t][3], off + AWT);
    }

    float sf[16][4];
#pragma unroll
    for (int nj = 0; nj < 16; nj++)
#pragma unroll
        for (int e = 0; e < 4; e++) sf[nj][e] = 0.f;

    int br = (lid & 7) + (lid >> 4) * 8;
#pragma unroll
    for (int t = 0; t < 4; t++) {
        int bc = t * 32 + ((lid >> 3) & 1) * 16;
#pragma unroll
        for (int p = 0; p < 8; p++) {
            uint32_t b0, b1, b2, b3, c0, c1, c2, c3;
            uint32_t ad = Kh_ + (p * 16 + br) * KR + bc;
            LDSM4(b0, b1, b2, b3, ad);
            LDSM4(c0, c1, c2, c3, ad + AWT);
            uint32_t Bh0[2] = {b0, b1}, Bh1[2] = {b2, b3};
            uint32_t Bl0[2] = {c0, c1}, Bl1[2] = {c2, c3};
            mma16816(sf[2*p],   qfh[t], Bh0);
            mma16816(sf[2*p],   qfh[t], Bl0);
            mma16816(sf[2*p],   qfl[t], Bh0);
            mma16816(sf[2*p+1], qfh[t], Bh1);
            mma16816(sf[2*p+1], qfh[t], Bl1);
            mma16816(sf[2*p+1], qfl[t], Bh1);
        }
    }

    float mr2[2], inv2[2];
#pragma unroll
    for (int h = 0; h < 2; h++) {
        int r = q0 + wid * 16 + (lid >> 2) + 8 * h;
        mr2[h]  = gm[bh * Sn + r];
        inv2[h] = 1.f / gl[bh * Sn + r];
    }
    const float scale = 0.125f;
    bool diag = (kt == qt);
#pragma unroll
    for (int nj = 0; nj < 16; nj++) {
#pragma unroll
        for (int h = 0; h < 2; h++) {
            int r  = q0 + wid * 16 + (lid >> 2) + 8 * h;
            int cc = k0 + nj * 8 + 2 * (lid & 3);
            float p0 = __expf(sf[nj][2*h]   * scale - mr2[h]) * inv2[h];
            float p1 = __expf(sf[nj][2*h+1] * scale - mr2[h]) * inv2[h];
            if (diag) {
                if (cc > r)     p0 = 0.f;
                if (cc + 1 > r) p1 = 0.f;
            }
            float2 v; v.x = p0; v.y = p1;
            *(float2*)&arow[(size_t)r * Sn + cc] = v;
        }
    }
}

// ---------------------------------------------------------------------------
extern "C" void kernel_launch(void* const* d_in, const int* in_sizes, int n_in,
                              void* d_out, int out_size)
{
    const float* query = (const float*)d_in[0];
    const float* key   = (const float*)d_in[1];
    const float* value = (const float*)d_in[2];
    // d_in[3] = causal mask, applied analytically
    const float* Wq = (const float*)d_in[4];
    const float* bq = (const float*)d_in[5];
    const float* Wk = (const float*)d_in[6];
    const float* bk = (const float*)d_in[7];
    const float* Wv = (const float*)d_in[8];
    const float* bv = (const float*)d_in[9];
    const float* Wo = (const float*)d_in[10];
    const float* bo = (const float*)d_in[11];

    __nv_bfloat16 *pqh,*pql,*pkh,*pkl,*pvh,*pvl,*pch,*pcl,*pAh,*pAl,*pWh,*pWl;
    float *pm, *pl;
    cudaGetSymbolAddress((void**)&pqh, g_qh);  cudaGetSymbolAddress((void**)&pql, g_ql);
    cudaGetSymbolAddress((void**)&pkh, g_kh);  cudaGetSymbolAddress((void**)&pkl, g_kl);
    cudaGetSymbolAddress((void**)&pvh, g_vh);  cudaGetSymbolAddress((void**)&pvl, g_vl);
    cudaGetSymbolAddress((void**)&pch, g_ctxh);cudaGetSymbolAddress((void**)&pcl, g_ctxl);
    cudaGetSymbolAddress((void**)&pAh, g_Ahi); cudaGetSymbolAddress((void**)&pAl, g_Alo);
    cudaGetSymbolAddress((void**)&pWh, g_Whi); cudaGetSymbolAddress((void**)&pWl, g_Wlo);
    cudaGetSymbolAddress((void**)&pm,  g_m);   cudaGetSymbolAddress((void**)&pl,  g_l);

    static bool attr_set = false;
    if (!attr_set) {
        cudaFuncSetAttribute(gemm_bf16_split,
                             cudaFuncAttributeMaxDynamicSharedMemorySize, GSMEM);
        cudaFuncSetAttribute(attn_pass1,
                             cudaFuncAttributeMaxDynamicSharedMemorySize, P1SMEM);
        cudaFuncSetAttribute(attn_write,
                             cudaFuncAttributeMaxDynamicSharedMemorySize, AWSMEM);
        attr_set = true;
    }

    const int NA4 = (Mn * En) / 4;
    const int NW4 = (En * En) / 4;
    dim3 gg(En / 128, Mn / 128);   // (8, 32)

    // QKV projections -> bf16 hi/lo in [B,H,S,D]
    auto proj = [&](const float* A, const float* W, const float* bias,
                    __nv_bfloat16* oH, __nv_bfloat16* oL) {
        split_bf16<<<(NA4 + 255) / 256, 256>>>((const float4*)A,
                                               (__nv_bfloat162*)pAh,
                                               (__nv_bfloat162*)pAl, NA4);
        split_bf16<<<(NW4 + 255) / 256, 256>>>((const float4*)W,
                                               (__nv_bfloat162*)pWh,
                                               (__nv_bfloat162*)pWl, NW4);
        gemm_bf16_split<<<gg, 256, GSMEM>>>(pAh, pAl, pWh, pWl, bias,
                                            nullptr, oH, oL, 1);
    };
    proj(query, Wq, bq, pqh, pql);
    proj(key,   Wk, bk, pkh, pkl);
    proj(value, Wv, bv, pvh, pvl);

    attn_pass1<<<dim3(Sn / 128, BHn), 256, P1SMEM>>>(pqh, pql, pkh, pkl, pvh, pvl,
                                                     pch, pcl, pm, pl);

    const size_t OUT_ELEMS  = (size_t)Bn * Sn * En;
    const size_t ATTN_ELEMS = (size_t)BHn * Sn * Sn;
    float* outp  = (float*)d_out;
    float* attnp = nullptr;
    if ((size_t)out_size >= OUT_ELEMS + ATTN_ELEMS) {
        attnp = outp + OUT_ELEMS;
    } else if ((size_t)out_size == ATTN_ELEMS) {
        attnp = outp; outp = nullptr;
    }

    if (attnp)
        attn_write<<<dim3(Sn / 128, Sn / 128, BHn), 256, AWSMEM>>>(
            pqh, pql, pkh, pkl, pm, pl, attnp);

    if (outp) {
        split_bf16<<<(NW4 + 255) / 256, 256>>>((const float4*)Wo,
                                               (__nv_bfloat162*)pWh,
                                               (__nv_bfloat162*)pWl, NW4);
        gemm_bf16_split<<<gg, 256, GSMEM>>>(pch, pcl, pWh, pWl, bo,
                                            outp, nullptr, nullptr, 0);
    }
}

// round 5
// speedup vs baseline: 2.2601x; 1.0107x over previous
#include <cuda_runtime.h>
#include <cuda_bf16.h>
#include <math.h>
#include <stdint.h>

#define Bn 2
#define Sn 2048
#define En 1024
#define Hn 16
#define Dn 64
#define Mn (Bn*Sn)    // 4096
#define BHn (Bn*Hn)   // 32

// ---------------- scratch (device globals; no allocation allowed) ----------
__device__ __nv_bfloat16 g_qh[(size_t)BHn*Sn*Dn], g_ql[(size_t)BHn*Sn*Dn];
__device__ __nv_bfloat16 g_kh[(size_t)BHn*Sn*Dn], g_kl[(size_t)BHn*Sn*Dn];
__device__ __nv_bfloat16 g_vh[(size_t)BHn*Sn*Dn], g_vl[(size_t)BHn*Sn*Dn];
__device__ __nv_bfloat16 g_ctxh[(size_t)Mn*En],   g_ctxl[(size_t)Mn*En];
__device__ __nv_bfloat16 g_Ahi[(size_t)Mn*En],    g_Alo[(size_t)Mn*En];
__device__ __nv_bfloat16 g_Whi[(size_t)En*En],    g_Wlo[(size_t)En*En];
__device__ float g_m[BHn*Sn];
__device__ float g_l[BHn*Sn];

// ---------------- PTX helpers (base-target only) ---------------------------
__device__ __forceinline__ uint32_t smem_u32(const void* p) {
    uint32_t a;
    asm("{ .reg .u64 t; cvta.to.shared.u64 t, %1; cvt.u32.u64 %0, t; }"
        : "=r"(a) : "l"(p));
    return a;
}
#define CP16(dst, src) \
    asm volatile("cp.async.cg.shared.global [%0], [%1], 16;\n" :: "r"(dst), "l"(src))
#define CP_COMMIT() asm volatile("cp.async.commit_group;\n" ::)
#define CP_WAIT0()  asm volatile("cp.async.wait_group 0;\n" ::)
#define CP_WAIT1()  asm volatile("cp.async.wait_group 1;\n" ::)
#define CP_WAIT2()  asm volatile("cp.async.wait_group 2;\n" ::)
#define LDSM4(R0, R1, R2, R3, A) \
    asm volatile("ldmatrix.sync.aligned.m8n8.x4.shared.b16 {%0,%1,%2,%3}, [%4];" \
                 : "=r"(R0), "=r"(R1), "=r"(R2), "=r"(R3) : "r"(A))
#define LDSM4T(R0, R1, R2, R3, A) \
    asm volatile("ldmatrix.sync.aligned.m8n8.x4.trans.shared.b16 {%0,%1,%2,%3}, [%4];" \
                 : "=r"(R0), "=r"(R1), "=r"(R2), "=r"(R3) : "r"(A))

__device__ __forceinline__ void mma16816(float* c, const uint32_t* a, const uint32_t* b) {
    asm volatile(
        "mma.sync.aligned.m16n8k16.row.col.f32.bf16.bf16.f32 "
        "{%0,%1,%2,%3}, {%4,%5,%6,%7}, {%8,%9}, {%0,%1,%2,%3};"
        : "+f"(c[0]), "+f"(c[1]), "+f"(c[2]), "+f"(c[3])
        : "r"(a[0]), "r"(a[1]), "r"(a[2]), "r"(a[3]), "r"(b[0]), "r"(b[1]));
}

// ===========================================================================
// Split fp32 -> (hi, lo) bf16 pair.  2 float4 per thread for ILP.
// ===========================================================================
__global__ void split_bf16(const float4* __restrict__ x,
                           __nv_bfloat162* __restrict__ hi,
                           __nv_bfloat162* __restrict__ lo, int n4)
{
    int i0 = (blockIdx.x * blockDim.x + threadIdx.x) * 2;
#pragma unroll
    for (int u = 0; u < 2; u++) {
        int i = i0 + u;
        if (i >= n4) return;
        float4 v = x[i];
        __nv_bfloat16 h0 = __float2bfloat16(v.x), h1 = __float2bfloat16(v.y);
        __nv_bfloat16 h2 = __float2bfloat16(v.z), h3 = __float2bfloat16(v.w);
        hi[i * 2 + 0] = __halves2bfloat162(h0, h1);
        hi[i * 2 + 1] = __halves2bfloat162(h2, h3);
        lo[i * 2 + 0] = __halves2bfloat162(
            __float2bfloat16(v.x - __bfloat162float(h0)),
            __float2bfloat16(v.y - __bfloat162float(h1)));
        lo[i * 2 + 1] = __halves2bfloat162(
            __float2bfloat16(v.z - __bfloat162float(h2)),
            __float2bfloat16(v.w - __bfloat162float(h3)));
    }
}

// ===========================================================================
// Tensor-core GEMM: C = A * W^T + bias, 3-term bf16 split.
// 4-stage cp.async pipeline, ONE barrier per stage.
// mode 0: fp32 out row-major [M, En]
// mode 1: bf16 hi/lo out in head-split layout [B, H, S, D]
// ===========================================================================
#define KC     32
#define TROW   80
#define TTEN   (128 * TROW)
#define TSTAGE (4 * TTEN)      // 40960
#define NPIPE  4
#define GSMEM  (NPIPE * TSTAGE)  // 163840

__global__ __launch_bounds__(256, 1)
void gemm_bf16_split(const __nv_bfloat16* __restrict__ Ah,
                     const __nv_bfloat16* __restrict__ Al,
                     const __nv_bfloat16* __restrict__ Wh,
                     const __nv_bfloat16* __restrict__ Wl,
                     const float* __restrict__ bias,
                     float* __restrict__ out,
                     __nv_bfloat16* __restrict__ oH,
                     __nv_bfloat16* __restrict__ oL, int mode)
{
    extern __shared__ __align__(128) char sm[];
    uint32_t sbase = smem_u32(sm);
    const int tid = threadIdx.x, wid = tid >> 5, lid = tid & 31;
    const int n0 = blockIdx.x * 128, m0 = blockIdx.y * 128;
    const int wm = wid & 3, wn = wid >> 2;

    const char* src[4] = { (const char*)(Ah + (size_t)m0 * En),
                           (const char*)(Al + (size_t)m0 * En),
                           (const char*)(Wh + (size_t)n0 * En),
                           (const char*)(Wl + (size_t)n0 * En) };

    auto fill = [&](int buf, int ks) {
        uint32_t st = sbase + buf * TSTAGE;
        size_t koff = (size_t)ks * (KC * 2);
#pragma unroll
        for (int it = 0; it < 8; it++) {
            int idx = tid + it * 256;
            int t = idx >> 9;
            int rc = idx & 511;
            int r = rc >> 2, c = rc & 3;
            CP16(st + t * TTEN + r * TROW + c * 16,
                 src[t] + koff + (size_t)r * 2048 + c * 16);
        }
        CP_COMMIT();
    };

    float acc[2][8][4];
#pragma unroll
    for (int mi = 0; mi < 2; mi++)
#pragma unroll
        for (int nj = 0; nj < 8; nj++)
#pragma unroll
            for (int q = 0; q < 4; q++) acc[mi][nj][q] = 0.f;

    fill(0, 0); fill(1, 1); fill(2, 2);   // 3-deep prologue

    const int NST = En / KC;   // 32
    for (int s = 0; s < NST; s++) {
        int buf = s & 3;
        CP_WAIT2();            // stage s resident
        __syncthreads();       // also protects buffer (s-1)%4 for refill below
        if (s + 3 < NST) fill((s + 3) & 3, s + 3);

        uint32_t Ab  = sbase + buf * TSTAGE;
        uint32_t Alb = Ab + TTEN;
        uint32_t Wb  = Ab + 2 * TTEN;
        uint32_t Wlb = Ab + 3 * TTEN;

#pragma unroll
        for (int kb = 0; kb < KC; kb += 16) {
            uint32_t ah[2][4], al[2][4];
            {
                int arow = wm * 32 + (lid & 7) + ((lid >> 3) & 1) * 8;
                int acol = kb + (lid >> 4) * 8;
                uint32_t aoff = arow * TROW + acol * 2;
#pragma unroll
                for (int mi = 0; mi < 2; mi++) {
                    LDSM4(ah[mi][0], ah[mi][1], ah[mi][2], ah[mi][3],
                          Ab + mi * (16 * TROW) + aoff);
                    LDSM4(al[mi][0], al[mi][1], al[mi][2], al[mi][3],
                          Alb + mi * (16 * TROW) + aoff);
                }
            }
            uint32_t bh[8][2], bl[8][2];
            {
                int brow = wn * 64 + (lid & 7) + (lid >> 4) * 8;
                int bcol = kb + ((lid >> 3) & 1) * 8;
                uint32_t boff = brow * TROW + bcol * 2;
#pragma unroll
                for (int p = 0; p < 4; p++) {
                    uint32_t r0, r1, r2, r3;
                    LDSM4(r0, r1, r2, r3, Wb + p * (16 * TROW) + boff);
                    bh[p * 2][0] = r0; bh[p * 2][1] = r1;
                    bh[p * 2 + 1][0] = r2; bh[p * 2 + 1][1] = r3;
                    LDSM4(r0, r1, r2, r3, Wlb + p * (16 * TROW) + boff);
                    bl[p * 2][0] = r0; bl[p * 2][1] = r1;
                    bl[p * 2 + 1][0] = r2; bl[p * 2 + 1][1] = r3;
                }
            }
#pragma unroll
            for (int mi = 0; mi < 2; mi++)
#pragma unroll
                for (int nj = 0; nj < 8; nj++) {
                    mma16816(acc[mi][nj], ah[mi], bh[nj]);
                    mma16816(acc[mi][nj], ah[mi], bl[nj]);
                    mma16816(acc[mi][nj], al[mi], bh[nj]);
                }
        }
    }

    int m_base = m0 + wm * 32;
    int n_base = n0 + wn * 64;
    int rsub = lid >> 2, csub = (lid & 3) * 2;
#pragma unroll
    for (int mi = 0; mi < 2; mi++) {
#pragma unroll
        for (int nj = 0; nj < 8; nj++) {
            int cc = n_base + nj * 8 + csub;
            float bx = bias[cc], by = bias[cc + 1];
#pragma unroll
            for (int half = 0; half < 2; half++) {
                int m = m_base + mi * 16 + rsub + half * 8;
                float vx = acc[mi][nj][half * 2 + 0] + bx;
                float vy = acc[mi][nj][half * 2 + 1] + by;
                if (mode == 0) {
                    float2 v; v.x = vx; v.y = vy;
                    *(float2*)&out[(size_t)m * En + cc] = v;
                } else {
                    int h = cc >> 6, d = cc & 63;
                    int b = m >> 11, ss = m & 2047;
                    size_t idx = (((size_t)b * Hn + h) * Sn + ss) * Dn + d;
                    __nv_bfloat162 hi = __floats2bfloat162_rn(vx, vy);
                    __nv_bfloat162 lo = __floats2bfloat162_rn(
                        vx - __bfloat162float(hi.x), vy - __bfloat162float(hi.y));
                    *(uint32_t*)&oH[idx] = *(uint32_t*)&hi;
                    *(uint32_t*)&oL[idx] = *(uint32_t*)&lo;
                }
            }
        }
    }
}

// ===========================================================================
// Flash pass 1 on tensor cores. CTA: 128 q-rows, 8 warps, 64-key tiles,
// 3-stage cp.async KV pipeline, one barrier per tile.
// ===========================================================================
#define KR 144
#define QSM (128*KR)
#define KVT (64*KR)
#define KVSTG (4*KVT)               // 36864
#define P1SMEM (2*QSM + 3*KVSTG)    // 147456

__global__ __launch_bounds__(256, 1)
void attn_pass1(const __nv_bfloat16* __restrict__ qh, const __nv_bfloat16* __restrict__ ql,
                const __nv_bfloat16* __restrict__ kh, const __nv_bfloat16* __restrict__ kl,
                const __nv_bfloat16* __restrict__ vh, const __nv_bfloat16* __restrict__ vl,
                __nv_bfloat16* __restrict__ ctxh, __nv_bfloat16* __restrict__ ctxl,
                float* __restrict__ gm, float* __restrict__ gl)
{
    extern __shared__ __align__(128) char sm[];
    uint32_t sb = smem_u32(sm);
    const int tid = threadIdx.x, wid = tid >> 5, lid = tid & 31;
    const int qt = (gridDim.x - 1) - blockIdx.x;
    const int bh = blockIdx.y;
    const int q0 = qt * 128;
    const size_t hbase = (size_t)bh * Sn * Dn;

    const char* gq[2]  = { (const char*)(qh + hbase + (size_t)q0 * Dn),
                           (const char*)(ql + hbase + (size_t)q0 * Dn) };
    const char* gkv[4] = { (const char*)(kh + hbase), (const char*)(kl + hbase),
                           (const char*)(vh + hbase), (const char*)(vl + hbase) };

    uint32_t Qb = sb, KVb = sb + 2 * QSM;

    // Q fill (joins first KV commit group)
#pragma unroll
    for (int i = 0; i < 8; i++) {
        int idx = tid + i * 256;
        int t = idx >> 10, rc = idx & 1023, r = rc >> 3, c = rc & 7;
        CP16(Qb + t * QSM + r * KR + c * 16, gq[t] + (size_t)r * 128 + c * 16);
    }
    auto fillKV = [&](int buf, int kt) {
        uint32_t st = KVb + buf * KVSTG;
        size_t gof = (size_t)kt * 64 * 128;
#pragma unroll
        for (int i = 0; i < 8; i++) {
            int idx = tid + i * 256;
            int t = idx >> 9, rc = idx & 511, r = rc >> 3, c = rc & 7;
            CP16(st + t * KVT + r * KR + c * 16, gkv[t] + gof + (size_t)r * 128 + c * 16);
        }
        CP_COMMIT();
    };
    const int ktmax = 2 * qt + 1;
    fillKV(0, 0);
    fillKV(1, 1);     // ktmax >= 1 always

    uint32_t qfh[4][4], qfl[4][4];
    float o[8][4];
#pragma unroll
    for (int nj = 0; nj < 8; nj++)
#pragma unroll
        for (int e = 0; e < 4; e++) o[nj][e] = 0.f;
    float mrow[2] = {-1e30f, -1e30f}, lrow[2] = {0.f, 0.f};

    for (int kt = 0; kt <= ktmax; kt++) {
        int buf = kt % 3;
        CP_WAIT1();
        __syncthreads();
        if (kt + 2 <= ktmax) fillKV((kt + 2) % 3, kt + 2);
        if (kt == 0) {
            int ar = wid * 16 + (lid & 7) + ((lid >> 3) & 1) * 8;
#pragma unroll
            for (int t = 0; t < 4; t++) {
                uint32_t off = Qb + ar * KR + t * 32 + (lid >> 4) * 16;
                LDSM4(qfh[t][0], qfh[t][1], qfh[t][2], qfh[t][3], off);
                LDSM4(qfl[t][0], qfl[t][1], qfl[t][2], qfl[t][3], off + QSM);
            }
        }
        uint32_t Kh_ = KVb + buf * KVSTG;
        uint32_t Vh_ = Kh_ + 2 * KVT;

        // ---- S = Q K^T (3-term) ----
        float sf[8][4];
#pragma unroll
        for (int nj = 0; nj < 8; nj++)
#pragma unroll
            for (int e = 0; e < 4; e++) sf[nj][e] = 0.f;

        int br = (lid & 7) + (lid >> 4) * 8;
#pragma unroll
        for (int t = 0; t < 4; t++) {
            int bc = t * 32 + ((lid >> 3) & 1) * 16;
#pragma unroll
            for (int p = 0; p < 4; p++) {
                uint32_t b0, b1, b2, b3, c0, c1, c2, c3;
                uint32_t ad = Kh_ + (p * 16 + br) * KR + bc;
                LDSM4(b0, b1, b2, b3, ad);
                LDSM4(c0, c1, c2, c3, ad + KVT);
                uint32_t Bh0[2] = {b0, b1}, Bh1[2] = {b2, b3};
                uint32_t Bl0[2] = {c0, c1}, Bl1[2] = {c2, c3};
                mma16816(sf[2*p],   qfh[t], Bh0);
                mma16816(sf[2*p],   qfh[t], Bl0);
                mma16816(sf[2*p],   qfl[t], Bh0);
                mma16816(sf[2*p+1], qfh[t], Bh1);
                mma16816(sf[2*p+1], qfh[t], Bl1);
                mma16816(sf[2*p+1], qfl[t], Bh1);
            }
        }

        // ---- online softmax ----
        const float scale = 0.125f;
        bool domask = (kt * 64 + 63) > (q0 + wid * 16);
        float tmax[2] = {-1e30f, -1e30f};
#pragma unroll
        for (int nj = 0; nj < 8; nj++)
#pragma unroll
            for (int e = 0; e < 4; e++) {
                float s = sf[nj][e] * scale;
                if (domask) {
                    int kc = kt * 64 + nj * 8 + 2 * (lid & 3) + (e & 1);
                    int qr = q0 + wid * 16 + (lid >> 2) + 8 * (e >> 1);
                    if (kc > qr) s = -1e9f;
                }
                sf[nj][e] = s;
                tmax[e >> 1] = fmaxf(tmax[e >> 1], s);
            }
#pragma unroll
        for (int h = 0; h < 2; h++) {
            tmax[h] = fmaxf(tmax[h], __shfl_xor_sync(0xffffffffu, tmax[h], 1));
            tmax[h] = fmaxf(tmax[h], __shfl_xor_sync(0xffffffffu, tmax[h], 2));
        }
        float fac[2], rsum[2] = {0.f, 0.f};
#pragma unroll
        for (int h = 0; h < 2; h++) {
            float mn = fmaxf(mrow[h], tmax[h]);
            fac[h] = __expf(mrow[h] - mn);
            mrow[h] = mn;
        }
#pragma unroll
        for (int nj = 0; nj < 8; nj++)
#pragma unroll
            for (int e = 0; e < 4; e++) {
                float p = __expf(sf[nj][e] - mrow[e >> 1]);
                sf[nj][e] = p;
                rsum[e >> 1] += p;
            }
#pragma unroll
        for (int h = 0; h < 2; h++) {
            rsum[h] += __shfl_xor_sync(0xffffffffu, rsum[h], 1);
            rsum[h] += __shfl_xor_sync(0xffffffffu, rsum[h], 2);
            lrow[h] = lrow[h] * fac[h] + rsum[h];
        }
#pragma unroll
        for (int nj = 0; nj < 8; nj++)
#pragma unroll
            for (int e = 0; e < 4; e++) o[nj][e] *= fac[e >> 1];

        // ---- O += P V (3-term) ----
        int vr = (lid & 7) + ((lid >> 3) & 1) * 8;
        int vc = (lid >> 4) * 16;
#pragma unroll
        for (int t = 0; t < 4; t++) {
            uint32_t pha[4], pla[4];
#pragma unroll
            for (int u = 0; u < 2; u++) {
                float x0 = sf[2*t+u][0], x1 = sf[2*t+u][1];
                float x2 = sf[2*t+u][2], x3 = sf[2*t+u][3];
                __nv_bfloat162 h01 = __floats2bfloat162_rn(x0, x1);
                __nv_bfloat162 h23 = __floats2bfloat162_rn(x2, x3);
                pha[2*u+0] = *(uint32_t*)&h01;
                pha[2*u+1] = *(uint32_t*)&h23;
                __nv_bfloat162 l01 = __floats2bfloat162_rn(
                    x0 - __bfloat162float(h01.x), x1 - __bfloat162float(h01.y));
                __nv_bfloat162 l23 = __floats2bfloat162_rn(
                    x2 - __bfloat162float(h23.x), x3 - __bfloat162float(h23.y));
                pla[2*u+0] = *(uint32_t*)&l01;
                pla[2*u+1] = *(uint32_t*)&l23;
            }
#pragma unroll
            for (int p = 0; p < 4; p++) {
                uint32_t b0, b1, b2, b3, c0, c1, c2, c3;
                uint32_t ad = Vh_ + (t * 16 + vr) * KR + p * 32 + vc;
                LDSM4T(b0, b1, b2, b3, ad);
                LDSM4T(c0, c1, c2, c3, ad + KVT);
                uint32_t Bh0[2] = {b0, b1}, Bh1[2] = {b2, b3};
                uint32_t Bl0[2] = {c0, c1}, Bl1[2] = {c2, c3};
                mma16816(o[2*p],   pha, Bh0);
                mma16816(o[2*p],   pha, Bl0);
                mma16816(o[2*p],   pla, Bh0);
                mma16816(o[2*p+1], pha, Bh1);
                mma16816(o[2*p+1], pha, Bl1);
                mma16816(o[2*p+1], pla, Bh1);
            }
        }
    }

    float invl[2] = {1.f / lrow[0], 1.f / lrow[1]};
    int b = bh >> 4, hh = bh & 15;
#pragma unroll
    for (int h = 0; h < 2; h++) {
        int r = q0 + wid * 16 + (lid >> 2) + 8 * h;
        size_t rowb = ((size_t)b * Sn + r) * En + hh * 64;
#pragma unroll
        for (int nj = 0; nj < 8; nj++) {
            int cc = nj * 8 + 2 * (lid & 3);
            float f0 = o[nj][2*h]   * invl[h];
            float f1 = o[nj][2*h+1] * invl[h];
            __nv_bfloat162 hi = __floats2bfloat162_rn(f0, f1);
            __nv_bfloat162 lo = __floats2bfloat162_rn(
                f0 - __bfloat162float(hi.x), f1 - __bfloat162float(hi.y));
            *(uint32_t*)&ctxh[rowb + cc] = *(uint32_t*)&hi;
            *(uint32_t*)&ctxl[rowb + cc] = *(uint32_t*)&lo;
        }
        if ((lid & 3) == 0) {
            gm[bh * Sn + r] = mrow[h];
            gl[bh * Sn + r] = lrow[h];
        }
    }
}

// ===========================================================================
// Pass 2: recompute P on tensor cores (3-term QK), write attn [BH,S,S].
// ===========================================================================
#define AWT   (128*KR)
#define AWSMEM (4*AWT)

__global__ __launch_bounds__(256, 1)
void attn_write(const __nv_bfloat16* __restrict__ qh, const __nv_bfloat16* __restrict__ ql,
                const __nv_bfloat16* __restrict__ kh, const __nv_bfloat16* __restrict__ kl,
                const float* __restrict__ gm, const float* __restrict__ gl,
                float* __restrict__ attn)
{
    const int kt = blockIdx.x, qt = blockIdx.y, bh = blockIdx.z;
    const int tid = threadIdx.x, wid = tid >> 5, lid = tid & 31;
    const int q0 = qt * 128, k0 = kt * 128;
    float* arow = attn + (size_t)bh * Sn * Sn;

    if (kt > qt) {
        float4 z = make_float4(0.f, 0.f, 0.f, 0.f);
#pragma unroll
        for (int i = 0; i < 16; i++) {
            int idx = tid + i * 256;
            int r = idx >> 5, c4 = (idx & 31) << 2;
            *(float4*)&arow[(size_t)(q0 + r) * Sn + k0 + c4] = z;
        }
        return;
    }

    extern __shared__ __align__(128) char sm[];
    uint32_t sb = smem_u32(sm);
    const size_t hbase = (size_t)bh * Sn * Dn;
    const char* gsrc[4] = { (const char*)(qh + hbase + (size_t)q0 * Dn),
                            (const char*)(ql + hbase + (size_t)q0 * Dn),
                            (const char*)(kh + hbase + (size_t)k0 * Dn),
                            (const char*)(kl + hbase + (size_t)k0 * Dn) };
#pragma unroll
    for (int i = 0; i < 16; i++) {
        int idx = tid + i * 256;
        int t = idx >> 10, rc = idx & 1023, r = rc >> 3, c = rc & 7;
        CP16(sb + t * AWT + r * KR + c * 16, gsrc[t] + (size_t)r * 128 + c * 16);
    }
    CP_COMMIT(); CP_WAIT0();
    __syncthreads();

    uint32_t Qh_ = sb, Kh_ = sb + 2 * AWT;

    uint32_t qfh[4][4], qfl[4][4];
    int ar = wid * 16 + (lid & 7) + ((lid >> 3) & 1) * 8;
#pragma unroll
    for (int t = 0; t < 4; t++) {
        uint32_t off = Qh_ + ar * KR + t * 32 + (lid >> 4) * 16;
        LDSM4(qfh[t][0], qfh[t][1], qfh[t][2], qfh[t][3], off);
        LDSM4(qfl[t][0], qfl[t][1], qfl[t][2], qfl[t][3], off + AWT);
    }

    float sf[16][4];
#pragma unroll
    for (int nj = 0; nj < 16; nj++)
#pragma unroll
        for (int e = 0; e < 4; e++) sf[nj][e] = 0.f;

    int br = (lid & 7) + (lid >> 4) * 8;
#pragma unroll
    for (int t = 0; t < 4; t++) {
        int bc = t * 32 + ((lid >> 3) & 1) * 16;
#pragma unroll
        for (int p = 0; p < 8; p++) {
            uint32_t b0, b1, b2, b3, c0, c1, c2, c3;
            uint32_t ad = Kh_ + (p * 16 + br) * KR + bc;
            LDSM4(b0, b1, b2, b3, ad);
            LDSM4(c0, c1, c2, c3, ad + AWT);
            uint32_t Bh0[2] = {b0, b1}, Bh1[2] = {b2, b3};
            uint32_t Bl0[2] = {c0, c1}, Bl1[2] = {c2, c3};
            mma16816(sf[2*p],   qfh[t], Bh0);
            mma16816(sf[2*p],   qfh[t], Bl0);
            mma16816(sf[2*p],   qfl[t], Bh0);
            mma16816(sf[2*p+1], qfh[t], Bh1);
            mma16816(sf[2*p+1], qfh[t], Bl1);
            mma16816(sf[2*p+1], qfl[t], Bh1);
        }
    }

    float mr2[2], inv2[2];
#pragma unroll
    for (int h = 0; h < 2; h++) {
        int r = q0 + wid * 16 + (lid >> 2) + 8 * h;
        mr2[h]  = gm[bh * Sn + r];
        inv2[h] = 1.f / gl[bh * Sn + r];
    }
    const float scale = 0.125f;
    bool diag = (kt == qt);
#pragma unroll
    for (int nj = 0; nj < 16; nj++) {
#pragma unroll
        for (int h = 0; h < 2; h++) {
            int r  = q0 + wid * 16 + (lid >> 2) + 8 * h;
            int cc = k0 + nj * 8 + 2 * (lid & 3);
            float p0 = __expf(sf[nj][2*h]   * scale - mr2[h]) * inv2[h];
            float p1 = __expf(sf[nj][2*h+1] * scale - mr2[h]) * inv2[h];
            if (diag) {
                if (cc > r)     p0 = 0.f;
                if (cc + 1 > r) p1 = 0.f;
            }
            float2 v; v.x = p0; v.y = p1;
            *(float2*)&arow[(size_t)r * Sn + cc] = v;
        }
    }
}

// ---------------------------------------------------------------------------
extern "C" void kernel_launch(void* const* d_in, const int* in_sizes, int n_in,
                              void* d_out, int out_size)
{
    const float* query = (const float*)d_in[0];
    const float* key   = (const float*)d_in[1];
    const float* value = (const float*)d_in[2];
    // d_in[3] = causal mask, applied analytically
    const float* Wq = (const float*)d_in[4];
    const float* bq = (const float*)d_in[5];
    const float* Wk = (const float*)d_in[6];
    const float* bk = (const float*)d_in[7];
    const float* Wv = (const float*)d_in[8];
    const float* bv = (const float*)d_in[9];
    const float* Wo = (const float*)d_in[10];
    const float* bo = (const float*)d_in[11];

    __nv_bfloat16 *pqh,*pql,*pkh,*pkl,*pvh,*pvl,*pch,*pcl,*pAh,*pAl,*pWh,*pWl;
    float *pm, *pl;
    cudaGetSymbolAddress((void**)&pqh, g_qh);  cudaGetSymbolAddress((void**)&pql, g_ql);
    cudaGetSymbolAddress((void**)&pkh, g_kh);  cudaGetSymbolAddress((void**)&pkl, g_kl);
    cudaGetSymbolAddress((void**)&pvh, g_vh);  cudaGetSymbolAddress((void**)&pvl, g_vl);
    cudaGetSymbolAddress((void**)&pch, g_ctxh);cudaGetSymbolAddress((void**)&pcl, g_ctxl);
    cudaGetSymbolAddress((void**)&pAh, g_Ahi); cudaGetSymbolAddress((void**)&pAl, g_Alo);
    cudaGetSymbolAddress((void**)&pWh, g_Whi); cudaGetSymbolAddress((void**)&pWl, g_Wlo);
    cudaGetSymbolAddress((void**)&pm,  g_m);   cudaGetSymbolAddress((void**)&pl,  g_l);

    static bool attr_set = false;
    if (!attr_set) {
        cudaFuncSetAttribute(gemm_bf16_split,
                             cudaFuncAttributeMaxDynamicSharedMemorySize, GSMEM);
        cudaFuncSetAttribute(attn_pass1,
                             cudaFuncAttributeMaxDynamicSharedMemorySize, P1SMEM);
        cudaFuncSetAttribute(attn_write,
                             cudaFuncAttributeMaxDynamicSharedMemorySize, AWSMEM);
        attr_set = true;
    }

    const int NA4 = (Mn * En) / 4;
    const int NW4 = (En * En) / 4;
    dim3 gg(En / 128, Mn / 128);   // (8, 32)

    auto proj = [&](const float* A, const float* W, const float* bias,
                    __nv_bfloat16* oH, __nv_bfloat16* oL) {
        split_bf16<<<(NA4/2 + 255) / 256, 256>>>((const float4*)A,
                                                 (__nv_bfloat162*)pAh,
                                                 (__nv_bfloat162*)pAl, NA4);
        split_bf16<<<(NW4/2 + 255) / 256, 256>>>((const float4*)W,
                                                 (__nv_bfloat162*)pWh,
                                                 (__nv_bfloat162*)pWl, NW4);
        gemm_bf16_split<<<gg, 256, GSMEM>>>(pAh, pAl, pWh, pWl, bias,
                                            nullptr, oH, oL, 1);
    };
    proj(query, Wq, bq, pqh, pql);
    proj(key,   Wk, bk, pkh, pkl);
    proj(value, Wv, bv, pvh, pvl);

    attn_pass1<<<dim3(Sn / 128, BHn), 256, P1SMEM>>>(pqh, pql, pkh, pkl, pvh, pvl,
                                                     pch, pcl, pm, pl);

    const size_t OUT_ELEMS  = (size_t)Bn * Sn * En;
    const size_t ATTN_ELEMS = (size_t)BHn * Sn * Sn;
    float* outp  = (float*)d_out;
    float* attnp = nullptr;
    if ((size_t)out_size >= OUT_ELEMS + ATTN_ELEMS) {
        attnp = outp + OUT_ELEMS;
    } else if ((size_t)out_size == ATTN_ELEMS) {
        attnp = outp; outp = nullptr;
    }

    if (attnp)
        attn_write<<<dim3(Sn / 128, Sn / 128, BHn), 256, AWSMEM>>>(
            pqh, pql, pkh, pkl, pm, pl, attnp);

    if (outp) {
        split_bf16<<<(NW4/2 + 255) / 256, 256>>>((const float4*)Wo,
                                                 (__nv_bfloat162*)pWh,
                                                 (__nv_bfloat162*)pWl, NW4);
        gemm_bf16_split<<<gg, 256, GSMEM>>>(pch, pcl, pWh, pWl, bo,
                                            outp, nullptr, nullptr, 0);
    }
}